// round 10
// baseline (speedup 1.0000x reference)
#include <cuda_runtime.h>
#include <math.h>
#include <stdint.h>

#define BB 4
#define SS 4096
#define DD 1024
#define HH 16
#define DH 64
#define BSZ 128
#define NB 32
#define EPSF 1e-4f

// ---------------- scratch ----------------
__device__ float g_angles[BB*SS*HH];
__device__ int   g_idx[BB*SS*HH];
__device__ int   g_inv[BB*SS*HH];
__device__ float g_qk[(size_t)BB*SS*DD];    // sorted rows, k-permuted cols
__device__ float g_v [(size_t)BB*SS*DD];    // sorted rows, k-permuted cols
__device__ float g_outs[(size_t)BB*SS*DD];  // k-permuted cols (feeds O gemm)
__device__ float g_ch0[BB*SS*HH];
__device__ float g_xp[(size_t)BB*SS*DD];    // x, k-permuted
__device__ float g_wqp[DD*DD];
__device__ float g_wvp[DD*DD];
__device__ float g_wop[DD*DD];

__device__ __forceinline__ float tf32r(float x) {
    uint32_t u;
    asm("cvt.rna.tf32.f32 %0, %1;" : "=r"(u) : "f"(x));
    return __uint_as_float(u);
}
__device__ __forceinline__ uint32_t tf32u(float x) {
    uint32_t u;
    asm("cvt.rna.tf32.f32 %0, %1;" : "=r"(u) : "f"(x));
    return u;
}

__device__ __forceinline__ void mma_tf32(float4& d,
                                         uint32_t a0, uint32_t a1, uint32_t a2, uint32_t a3,
                                         uint32_t b0, uint32_t b1) {
    asm volatile(
        "mma.sync.aligned.m16n8k8.row.col.f32.tf32.tf32.f32 "
        "{%0,%1,%2,%3},{%4,%5,%6,%7},{%8,%9},{%0,%1,%2,%3};"
        : "+f"(d.x), "+f"(d.y), "+f"(d.z), "+f"(d.w)
        : "r"(a0), "r"(a1), "r"(a2), "r"(a3), "r"(b0), "r"(b1));
}

__device__ __forceinline__ void cpa16(uint32_t saddr, const float* g) {
    asm volatile("cp.async.cg.shared.global [%0], [%1], 16;\n" :: "r"(saddr), "l"(g));
}

// ---------------- 0) k-permute within 8-groups: [l0,l4,l1,l5,l2,l6,l3,l7] ----
__global__ void __launch_bounds__(256) perm8(const float* __restrict__ src,
                                             float* __restrict__ dst, int n8) {
    int i = blockIdx.x*256 + threadIdx.x;
    if (i >= n8) return;
    const float4* s = (const float4*)(src + (size_t)i*8);
    float4 lo = s[0], hi = s[1];
    float4* d = (float4*)(dst + (size_t)i*8);
    d[0] = make_float4(lo.x, hi.x, lo.y, hi.y);
    d[1] = make_float4(lo.z, hi.z, lo.w, hi.w);
}

// ---------------- 1) hash (exact fp32 serial chain, matches ref) ----------------
__global__ void __launch_bounds__(1024) hash_kernel(const float* __restrict__ x,
                                                    const float* __restrict__ Wh) {
    __shared__ float xs[32][257];
    __shared__ float hs[32][34];
    int g = threadIdx.x;
    int o = threadIdx.y;
    int tid = o * 32 + g;
    int tok0 = blockIdx.x * 32;
    const float* xbase = x + (size_t)tok0 * DD;
    float acc = 0.f;
    for (int c = 0; c < 4; c++) {
        __syncthreads();
        for (int i = tid; i < 32*64; i += 1024) {
            int r = i >> 6, cc = i & 63;
            float4 v = *(const float4*)(xbase + (size_t)r*DD + c*256 + cc*4);
            float* dst = &xs[r][cc*4];
            dst[0]=v.x; dst[1]=v.y; dst[2]=v.z; dst[3]=v.w;
        }
        __syncthreads();
        const float* w = Wh + (size_t)o*DD + c*256;
        #pragma unroll 8
        for (int k = 0; k < 256; k++)
            acc = fmaf(xs[g][k], __ldg(w + k), acc);
    }
    hs[g][o] = acc;
    __syncthreads();
    if (o < HH) {
        float h0 = hs[g][2*o], h1 = hs[g][2*o+1];
        g_angles[((size_t)(tok0 + g))*HH + o] = __fdiv_rn(h0, h1 + EPSF);
    }
}

// ---------------- 2) STABLE bitonic argsort + inverse ----------------
__global__ void __launch_bounds__(1024) sort_kernel() {
    int b = blockIdx.x / HH, h = blockIdx.x % HH;
    __shared__ float key[SS];
    __shared__ int   val[SS];
    int tid = threadIdx.x;
    for (int i = tid; i < SS; i += 1024) {
        key[i] = g_angles[((size_t)b*SS + i)*HH + h];
        val[i] = i;
    }
    __syncthreads();
    for (int k = 2; k <= SS; k <<= 1) {
        for (int j = k >> 1; j > 0; j >>= 1) {
            for (int i = tid; i < SS; i += 1024) {
                int ixj = i ^ j;
                if (ixj > i) {
                    bool up = ((i & k) == 0);
                    float ki = key[i], kj = key[ixj];
                    int   vi = val[i], vj = val[ixj];
                    bool gt = (ki > kj) || (ki == kj && vi > vj);
                    if (gt == up) {
                        key[i] = kj; key[ixj] = ki;
                        val[i] = vj; val[ixj] = vi;
                    }
                }
            }
            __syncthreads();
        }
    }
    for (int i = tid; i < SS; i += 1024) {
        int v = val[i];
        g_idx[((size_t)b*SS + i)*HH + h] = v;
        g_inv[((size_t)b*SS + v)*HH + h] = i;
    }
}

// ---------------- 3) TF32 GEMM: 128x128x32, 2-stage cp.async, permuted-k inputs ----
#define AST 40   // stride mod 32 == 8 -> conflict-free float2 frag loads

__global__ void __launch_bounds__(256, 2) gemm3(const float* __restrict__ A,
                                                const float* __restrict__ W0,
                                                const float* __restrict__ b0,
                                                float* __restrict__ C0,
                                                const float* __restrict__ W1,
                                                const float* __restrict__ b1,
                                                float* __restrict__ C1,
                                                int split, int N, int K, int mode) {
    extern __shared__ float smem[];
    float* As = smem;                        // [2][128][AST]
    float* Bs = smem + 2*128*AST;            // [2][128][AST]

    const float* W; const float* bias; float* C;
    int bx = blockIdx.x;
    if (bx < split) { W = W0; bias = b0; C = C0; }
    else            { W = W1; bias = b1; C = C1; bx -= split; }
    int bm = blockIdx.y * 128, bn = bx * 128;

    int tid  = threadIdx.x;
    int lane = tid & 31, wid = tid >> 5;
    int g = lane >> 2, tg = lane & 3;
    int warp_m = (wid & 1) * 64;
    int warp_n = (wid >> 1) * 32;

    float4 acc[4][4];
    #pragma unroll
    for (int i = 0; i < 4; i++)
        #pragma unroll
        for (int j = 0; j < 4; j++) acc[i][j] = make_float4(0.f,0.f,0.f,0.f);

    auto load_tile = [&](int k0, int buf) {
        uint32_t abase = (uint32_t)__cvta_generic_to_shared(As + buf*128*AST);
        uint32_t bbase = (uint32_t)__cvta_generic_to_shared(Bs + buf*128*AST);
        #pragma unroll
        for (int i = 0; i < 4; i++) {
            int idx = tid + i*256;
            int r = idx >> 3, c4 = (idx & 7) * 4;
            cpa16(abase + (r*AST + c4)*4, A + (size_t)(bm + r)*K + k0 + c4);
            cpa16(bbase + (r*AST + c4)*4, W + (size_t)(bn + r)*K + k0 + c4);
        }
        asm volatile("cp.async.commit_group;\n");
    };

    load_tile(0, 0);

    int nkt = K / 32;
    for (int kt = 0; kt < nkt; kt++) {
        int cur = kt & 1;
        if (kt + 1 < nkt) {
            load_tile((kt + 1) * 32, (kt + 1) & 1);
            asm volatile("cp.async.wait_group 1;\n");
        } else {
            asm volatile("cp.async.wait_group 0;\n");
        }
        __syncthreads();

        const float* Ab = As + cur*128*AST;
        const float* Bb = Bs + cur*128*AST;
        #pragma unroll
        for (int ks = 0; ks < 4; ks++) {
            int kc = ks * 8;
            uint32_t a[4][4], b[4][2];
            #pragma unroll
            for (int mt = 0; mt < 4; mt++) {
                int r0 = warp_m + mt*16;
                float2 f0 = *(const float2*)&Ab[(r0+g  )*AST + kc + 2*tg];
                float2 f1 = *(const float2*)&Ab[(r0+g+8)*AST + kc + 2*tg];
                a[mt][0]=tf32u(f0.x); a[mt][2]=tf32u(f0.y);
                a[mt][1]=tf32u(f1.x); a[mt][3]=tf32u(f1.y);
            }
            #pragma unroll
            for (int nt = 0; nt < 4; nt++) {
                float2 fb = *(const float2*)&Bb[(warp_n+nt*8+g)*AST + kc + 2*tg];
                b[nt][0]=tf32u(fb.x); b[nt][1]=tf32u(fb.y);
            }
            #pragma unroll
            for (int mt = 0; mt < 4; mt++)
                #pragma unroll
                for (int nt = 0; nt < 4; nt++)
                    mma_tf32(acc[mt][nt], a[mt][0],a[mt][1],a[mt][2],a[mt][3],
                             b[nt][0], b[nt][1]);
        }
        __syncthreads();
    }

    if (mode == 0) {
        // natural-layout output (final projection)
        #pragma unroll
        for (int mt = 0; mt < 4; mt++) {
            int r0 = bm + warp_m + mt*16 + g;
            #pragma unroll
            for (int nt = 0; nt < 4; nt++) {
                int col = bn + warp_n + nt*8 + 2*tg;
                float bx2 = __ldg(bias + col), by = __ldg(bias + col + 1);
                float4 c = acc[mt][nt];
                *(float2*)(C + (size_t)r0*N + col)     = make_float2(c.x + bx2, c.y + by);
                *(float2*)(C + (size_t)(r0+8)*N + col) = make_float2(c.z + bx2, c.w + by);
            }
        }
    } else {
        // permuted-col output + per-head sorted row scatter
        int hsel = (bn + warp_n) >> 6;
        int pc = ((tg & 1) << 2) | (tg >> 1);   // physical within-8 base for logical 2tg
        #pragma unroll
        for (int mt = 0; mt < 4; mt++) {
            int r0 = bm + warp_m + mt*16 + g;
            int r1 = r0 + 8;
            int p0 = g_inv[(size_t)r0*HH + hsel];
            int p1 = g_inv[(size_t)r1*HH + hsel];
            size_t o0 = ((size_t)(r0 & ~(SS-1)) + p0) * (size_t)N;
            size_t o1 = ((size_t)(r1 & ~(SS-1)) + p1) * (size_t)N;
            #pragma unroll
            for (int nt = 0; nt < 4; nt++) {
                int colL = bn + warp_n + nt*8 + 2*tg;        // logical (for bias)
                int colP = bn + warp_n + nt*8 + pc;          // physical (store)
                float bx2 = __ldg(bias + colL), by = __ldg(bias + colL + 1);
                float4 c = acc[mt][nt];
                C[o0 + colP]     = c.x + bx2;
                C[o0 + colP + 2] = c.y + by;
                C[o1 + colP]     = c.z + bx2;
                C[o1 + colP + 2] = c.w + by;
            }
        }
    }
}

// ---------------- 4) attention: permuted-k, float2 frags, 512 threads ----------------
#define SST 264   // mod 32 == 8
#define QST 72    // mod 32 == 8
#define VST 72

__global__ void __launch_bounds__(512) attn_kernel() {
    extern __shared__ float smem[];
    float* sS = smem;                    // 128 x SST (permuted cols)
    float* sQ = smem + 128*SST;          // 128 x QST
    float* sK = sQ + 128*QST;            // 128 x QST
    float* sV = sQ;                      // 256 x VST (exactly reuses Q+K region)

    int tid = threadIdx.x;
    int lane = tid & 31, wid = tid >> 5;
    int g = lane >> 2, tg = lane & 3;
    int warp_m  = (wid & 7) * 16;
    int warp_nS = (wid >> 3) * 64;
    int warp_nV = (wid >> 3) * 32;

    int n = blockIdx.x, h = blockIdx.y, b = blockIdx.z;
    int base = n * BSZ;
    const float* qkp = g_qk + (size_t)b*SS*DD + h*DH;
    const float* vp  = g_v  + (size_t)b*SS*DD + h*DH;
    const float scale = 0.03125f;

    uint32_t sqb = (uint32_t)__cvta_generic_to_shared(sQ);
    uint32_t skb = (uint32_t)__cvta_generic_to_shared(sK);
    uint32_t svb = (uint32_t)__cvta_generic_to_shared(sV);

    for (int p = tid; p < 128*16; p += 512) {
        int r = p >> 4, seg = p & 15;
        cpa16(sqb + (r*QST + seg*4)*4, qkp + (size_t)(base + r)*DD + seg*4);
    }
    for (int p = tid; p < 128*16; p += 512) {
        int r = p >> 4, seg = p & 15;
        cpa16(skb + (r*QST + seg*4)*4, qkp + (size_t)((base + r) & (SS-1))*DD + seg*4);
    }
    asm volatile("cp.async.commit_group;\n");
    asm volatile("cp.async.wait_group 0;\n");
    __syncthreads();

    int pc = ((tg & 1) << 2) | (tg >> 1);

    #pragma unroll 1
    for (int hf = 0; hf < 2; hf++) {
        if (hf == 1) {
            __syncthreads();
            for (int p = tid; p < 128*16; p += 512) {
                int r = p >> 4, seg = p & 15;
                cpa16(skb + (r*QST + seg*4)*4,
                      qkp + (size_t)((base + 128 + r) & (SS-1))*DD + seg*4);
            }
            asm volatile("cp.async.commit_group;\n");
            asm volatile("cp.async.wait_group 0;\n");
            __syncthreads();
        }
        float4 acc[8];
        #pragma unroll
        for (int j = 0; j < 8; j++) acc[j] = make_float4(0.f,0.f,0.f,0.f);

        #pragma unroll
        for (int ks = 0; ks < 8; ks++) {
            int kc = ks * 8;
            uint32_t a[4], bfr[8][2];
            {
                float2 f0 = *(const float2*)&sQ[(warp_m+g  )*QST + kc + 2*tg];
                float2 f1 = *(const float2*)&sQ[(warp_m+g+8)*QST + kc + 2*tg];
                a[0]=tf32u(f0.x); a[2]=tf32u(f0.y);
                a[1]=tf32u(f1.x); a[3]=tf32u(f1.y);
            }
            #pragma unroll
            for (int nt = 0; nt < 8; nt++) {
                float2 fb = *(const float2*)&sK[(warp_nS+nt*8+g)*QST + kc + 2*tg];
                bfr[nt][0]=tf32u(fb.x); bfr[nt][1]=tf32u(fb.y);
            }
            #pragma unroll
            for (int nt = 0; nt < 8; nt++)
                mma_tf32(acc[nt], a[0],a[1],a[2],a[3], bfr[nt][0], bfr[nt][1]);
        }
        {
            int i0 = warp_m + g;
            #pragma unroll
            for (int nt = 0; nt < 8; nt++) {
                int jb = warp_nS + nt*8;
                int j0 = jb + 2*tg;                 // logical
                float4 c = acc[nt];
                float* p0 = sS + i0*SST + hf*128 + jb;
                float* p1 = p0 + 8*SST;
                if (hf == 0) {
                    p0[pc]   = (j0   == i0  ) ? -INFINITY : c.x*scale;
                    p0[pc+2] = (j0+1 == i0  ) ? -INFINITY : c.y*scale;
                    p1[pc]   = (j0   == i0+8) ? -INFINITY : c.z*scale;
                    p1[pc+2] = (j0+1 == i0+8) ? -INFINITY : c.w*scale;
                } else {
                    p0[pc]   = c.x*scale; p0[pc+2] = c.y*scale;
                    p1[pc]   = c.z*scale; p1[pc+2] = c.w*scale;
                }
            }
        }
    }
    __syncthreads();   // scores in sS; sQ/sK free

    // V load (overlaps softmax)
    for (int p = tid; p < 256*16; p += 512) {
        int j = p >> 4, seg = p & 15;
        cpa16(svb + (j*VST + seg*4)*4, vp + (size_t)((base + j) & (SS-1))*DD + seg*4);
    }
    asm volatile("cp.async.commit_group;\n");

    // softmax (quarter-row per thread; permutation is order-agnostic)
    {
        int row = tid >> 2, q = tid & 3;
        float* rp = sS + row*SST + q*64;
        float mx = -INFINITY;
        #pragma unroll 4
        for (int c = 0; c < 16; c++) {
            float4 v = ((float4*)rp)[c];
            mx = fmaxf(mx, fmaxf(fmaxf(v.x,v.y), fmaxf(v.z,v.w)));
        }
        mx = fmaxf(mx, __shfl_xor_sync(0xffffffffu, mx, 1));
        mx = fmaxf(mx, __shfl_xor_sync(0xffffffffu, mx, 2));
        float sum = 0.f;
        #pragma unroll 4
        for (int c = 0; c < 16; c++) {
            float4 v = ((float4*)rp)[c];
            v.x = __expf(v.x - mx); v.y = __expf(v.y - mx);
            v.z = __expf(v.z - mx); v.w = __expf(v.w - mx);
            sum += (v.x + v.y) + (v.z + v.w);
            ((float4*)rp)[c] = v;
        }
        sum += __shfl_xor_sync(0xffffffffu, sum, 1);
        sum += __shfl_xor_sync(0xffffffffu, sum, 2);
        float inv = 1.f / sum;
        #pragma unroll 4
        for (int c = 0; c < 16; c++) {
            float4 v = ((float4*)rp)[c];
            v.x = tf32r(v.x*inv); v.y = tf32r(v.y*inv);
            v.z = tf32r(v.z*inv); v.w = tf32r(v.w*inv);
            ((float4*)rp)[c] = v;
        }
    }
    asm volatile("cp.async.wait_group 0;\n");
    __syncthreads();

    // PV: out[128x64] = P[128x256] @ V[256x64]; A-frags float2 (permuted sS)
    float4 o[4];
    #pragma unroll
    for (int j = 0; j < 4; j++) o[j] = make_float4(0.f,0.f,0.f,0.f);

    #pragma unroll 4
    for (int ks = 0; ks < 32; ks++) {
        int kc = ks * 8;
        uint32_t a[4], bfr[4][2];
        {
            float2 f0 = *(const float2*)&sS[(warp_m+g  )*SST + kc + 2*tg];
            float2 f1 = *(const float2*)&sS[(warp_m+g+8)*SST + kc + 2*tg];
            a[0]=__float_as_uint(f0.x); a[2]=__float_as_uint(f0.y);
            a[1]=__float_as_uint(f1.x); a[3]=__float_as_uint(f1.y);
        }
        #pragma unroll
        for (int nt = 0; nt < 4; nt++) {
            int n0 = warp_nV + nt*8;
            bfr[nt][0] = tf32u(sV[(kc+tg  )*VST + n0+g]);
            bfr[nt][1] = tf32u(sV[(kc+tg+4)*VST + n0+g]);
        }
        #pragma unroll
        for (int nt = 0; nt < 4; nt++)
            mma_tf32(o[nt], a[0],a[1],a[2],a[3], bfr[nt][0], bfr[nt][1]);
    }

    // epilogue: accumulator cols are PHYSICAL (permuted) V features; store as-is —
    // g_outs then matches the permuted-k layout the O-gemm expects.
    float* outp = g_outs + (size_t)b*SS*DD + h*DH;
    {
        int i0 = warp_m + g;
        int t0 = base + i0;
        #pragma unroll
        for (int nt = 0; nt < 4; nt++) {
            int d0 = warp_nV + nt*8 + 2*tg;
            float4 c = o[nt];
            *(float2*)(outp + (size_t)t0*DD + d0)     = make_float2(c.x, c.y);
            *(float2*)(outp + (size_t)(t0+8)*DD + d0) = make_float2(c.z, c.w);
            if (d0 == 0) {   // physical 0 == logical feature 0
                g_ch0[((size_t)b*SS + t0  )*HH + h] = c.x;
                g_ch0[((size_t)b*SS + t0+8)*HH + h] = c.z;
            }
        }
    }
}

// ---------------- 5) feature-0-only inverse scatter (physical col 0 == logical 0) ----
__global__ void __launch_bounds__(256) scatter_kernel() {
    int i = blockIdx.x*256 + threadIdx.x;
    if (i >= BB*SS*HH) return;
    int h = i % HH;
    int b = i / (SS*HH);
    int p = g_idx[i];
    g_outs[((size_t)b*SS + p)*DD + h*DH] = g_ch0[i];
}

// ---------------- launch ----------------
extern "C" void kernel_launch(void* const* d_in, const int* in_sizes, int n_in,
                              void* d_out, int out_size) {
    const float* x  = (const float*)d_in[0];
    const float* Wh = (const float*)d_in[1];
    const float* Wq = (const float*)d_in[2];
    const float* bq = (const float*)d_in[3];
    const float* Wv = (const float*)d_in[4];
    const float* bv = (const float*)d_in[5];
    const float* Wo = (const float*)d_in[6];
    const float* bo = (const float*)d_in[7];
    float* out = (float*)d_out;

    float* qkp; cudaGetSymbolAddress((void**)&qkp, g_qk);
    float* vp;  cudaGetSymbolAddress((void**)&vp,  g_v);
    float* osp; cudaGetSymbolAddress((void**)&osp, g_outs);
    float* xp;  cudaGetSymbolAddress((void**)&xp,  g_xp);
    float* wqp; cudaGetSymbolAddress((void**)&wqp, g_wqp);
    float* wvp; cudaGetSymbolAddress((void**)&wvp, g_wvp);
    float* wop; cudaGetSymbolAddress((void**)&wop, g_wop);

    const int M = BB*SS;

    // 0) permute inputs' k-dims within 8-groups
    int nx8 = (M*DD)/8, nw8 = (DD*DD)/8;
    perm8<<<(nx8+255)/256, 256>>>(x,  xp,  nx8);
    perm8<<<(nw8+255)/256, 256>>>(Wq, wqp, nw8);
    perm8<<<(nw8+255)/256, 256>>>(Wv, wvp, nw8);
    perm8<<<(nw8+255)/256, 256>>>(Wo, wop, nw8);

    hash_kernel<<<M/32, dim3(32,32)>>>(x, Wh);
    sort_kernel<<<BB*HH, 1024>>>();

    size_t gsmem = (size_t)(4*128*AST) * sizeof(float);   // 81,920 B (2 stages A+B)
    cudaFuncSetAttribute(gemm3, cudaFuncAttributeMaxDynamicSharedMemorySize, (int)gsmem);
    gemm3<<<dim3(16, M/128), 256, gsmem>>>(xp, wqp, bq, qkp, wvp, bv, vp, 8, DD, DD, 1);

    size_t asmem = (size_t)(128*SST + 2*128*QST) * sizeof(float);  // 208,896 B
    cudaFuncSetAttribute(attn_kernel, cudaFuncAttributeMaxDynamicSharedMemorySize, (int)asmem);
    dim3 ag(NB, HH, BB);
    attn_kernel<<<ag, 512, asmem>>>();

    scatter_kernel<<<(BB*SS*HH + 255)/256, 256>>>();
    gemm3<<<dim3(8, M/128), 256, gsmem>>>(osp, wop, bo, out, wop, bo, out, 8, DD, DD, 0);
}

// round 11
// speedup vs baseline: 1.0383x; 1.0383x over previous
#include <cuda_runtime.h>
#include <math.h>
#include <stdint.h>

#define BB 4
#define SS 4096
#define DD 1024
#define HH 16
#define DH 64
#define BSZ 128
#define NB 32
#define EPSF 1e-4f

// ---------------- scratch ----------------
__device__ float g_angles[BB*SS*HH];
__device__ int   g_idx[BB*SS*HH];
__device__ int   g_inv[BB*SS*HH];
__device__ float g_qk[(size_t)BB*SS*DD];    // sorted rows, k-permuted cols
__device__ float g_v [(size_t)BB*SS*DD];    // sorted rows, k-permuted cols
__device__ float g_outs[(size_t)BB*SS*DD];  // k-permuted cols (feeds O gemm)
__device__ float g_ch0[BB*SS*HH];
__device__ float g_wqp[DD*DD];
__device__ float g_wvp[DD*DD];
__device__ float g_wop[DD*DD];

__device__ __forceinline__ float tf32r(float x) {
    uint32_t u;
    asm("cvt.rna.tf32.f32 %0, %1;" : "=r"(u) : "f"(x));
    return __uint_as_float(u);
}
__device__ __forceinline__ uint32_t tf32u(float x) {
    uint32_t u;
    asm("cvt.rna.tf32.f32 %0, %1;" : "=r"(u) : "f"(x));
    return u;
}

__device__ __forceinline__ void mma_tf32(float4& d,
                                         uint32_t a0, uint32_t a1, uint32_t a2, uint32_t a3,
                                         uint32_t b0, uint32_t b1) {
    asm volatile(
        "mma.sync.aligned.m16n8k8.row.col.f32.tf32.tf32.f32 "
        "{%0,%1,%2,%3},{%4,%5,%6,%7},{%8,%9},{%0,%1,%2,%3};"
        : "+f"(d.x), "+f"(d.y), "+f"(d.z), "+f"(d.w)
        : "r"(a0), "r"(a1), "r"(a2), "r"(a3), "r"(b0), "r"(b1));
}

__device__ __forceinline__ void cpa16(uint32_t saddr, const float* g) {
    asm volatile("cp.async.cg.shared.global [%0], [%1], 16;\n" :: "r"(saddr), "l"(g));
}

// ---------------- 0) k-permute within 8-groups: [l0,l4,l1,l5,l2,l6,l3,l7] ----
__global__ void __launch_bounds__(256) perm8(const float* __restrict__ src,
                                             float* __restrict__ dst, int n8) {
    int i = blockIdx.x*256 + threadIdx.x;
    if (i >= n8) return;
    const float4* s = (const float4*)(src + (size_t)i*8);
    float4 lo = s[0], hi = s[1];
    float4* d = (float4*)(dst + (size_t)i*8);
    d[0] = make_float4(lo.x, hi.x, lo.y, hi.y);
    d[1] = make_float4(lo.z, hi.z, lo.w, hi.w);
}

// ---------------- 1) hash (exact fp32 serial chain, matches ref) ----------------
__global__ void __launch_bounds__(1024) hash_kernel(const float* __restrict__ x,
                                                    const float* __restrict__ Wh) {
    __shared__ float xs[32][257];
    __shared__ float hs[32][34];
    int g = threadIdx.x;
    int o = threadIdx.y;
    int tid = o * 32 + g;
    int tok0 = blockIdx.x * 32;
    const float* xbase = x + (size_t)tok0 * DD;
    float acc = 0.f;
    for (int c = 0; c < 4; c++) {
        __syncthreads();
        for (int i = tid; i < 32*64; i += 1024) {
            int r = i >> 6, cc = i & 63;
            float4 v = *(const float4*)(xbase + (size_t)r*DD + c*256 + cc*4);
            float* dst = &xs[r][cc*4];
            dst[0]=v.x; dst[1]=v.y; dst[2]=v.z; dst[3]=v.w;
        }
        __syncthreads();
        const float* w = Wh + (size_t)o*DD + c*256;
        #pragma unroll 8
        for (int k = 0; k < 256; k++)
            acc = fmaf(xs[g][k], __ldg(w + k), acc);
    }
    hs[g][o] = acc;
    __syncthreads();
    if (o < HH) {
        float h0 = hs[g][2*o], h1 = hs[g][2*o+1];
        g_angles[((size_t)(tok0 + g))*HH + o] = __fdiv_rn(h0, h1 + EPSF);
    }
}

// ---------------- 2) STABLE bitonic argsort + inverse ----------------
__global__ void __launch_bounds__(1024) sort_kernel() {
    int b = blockIdx.x / HH, h = blockIdx.x % HH;
    __shared__ float key[SS];
    __shared__ int   val[SS];
    int tid = threadIdx.x;
    for (int i = tid; i < SS; i += 1024) {
        key[i] = g_angles[((size_t)b*SS + i)*HH + h];
        val[i] = i;
    }
    __syncthreads();
    for (int k = 2; k <= SS; k <<= 1) {
        for (int j = k >> 1; j > 0; j >>= 1) {
            for (int i = tid; i < SS; i += 1024) {
                int ixj = i ^ j;
                if (ixj > i) {
                    bool up = ((i & k) == 0);
                    float ki = key[i], kj = key[ixj];
                    int   vi = val[i], vj = val[ixj];
                    bool gt = (ki > kj) || (ki == kj && vi > vj);
                    if (gt == up) {
                        key[i] = kj; key[ixj] = ki;
                        val[i] = vj; val[ixj] = vi;
                    }
                }
            }
            __syncthreads();
        }
    }
    for (int i = tid; i < SS; i += 1024) {
        int v = val[i];
        g_idx[((size_t)b*SS + i)*HH + h] = v;
        g_inv[((size_t)b*SS + v)*HH + h] = i;
    }
}

// ---------------- 3) TF32 GEMM: 128x128x32, 2-stage cp.async ----
// QV=true : A natural (scalar a-frags, stride 36), scatter+permute epilogue
// QV=false: A permuted (float2 a-frags, stride 40), natural epilogue
// B always permuted (float2 b-frags, stride 40)
#define ASTB 40

template<bool QV>
__global__ void __launch_bounds__(256, 2) gemm3(const float* __restrict__ A,
                                                const float* __restrict__ W0,
                                                const float* __restrict__ b0,
                                                float* __restrict__ C0,
                                                const float* __restrict__ W1,
                                                const float* __restrict__ b1,
                                                float* __restrict__ C1,
                                                int split, int N, int K) {
    constexpr int ASTA = QV ? 36 : 40;
    extern __shared__ float smem[];
    float* As = smem;                        // [2][128][ASTA]
    float* Bs = smem + 2*128*ASTA;           // [2][128][ASTB]

    const float* W; const float* bias; float* C;
    int bx = blockIdx.x;
    if (bx < split) { W = W0; bias = b0; C = C0; }
    else            { W = W1; bias = b1; C = C1; bx -= split; }
    int bm = blockIdx.y * 128, bn = bx * 128;

    int tid  = threadIdx.x;
    int lane = tid & 31, wid = tid >> 5;
    int g = lane >> 2, tg = lane & 3;
    int warp_m = (wid & 1) * 64;
    int warp_n = (wid >> 1) * 32;

    float4 acc[4][4];
    #pragma unroll
    for (int i = 0; i < 4; i++)
        #pragma unroll
        for (int j = 0; j < 4; j++) acc[i][j] = make_float4(0.f,0.f,0.f,0.f);

    auto load_tile = [&](int k0, int buf) {
        uint32_t abase = (uint32_t)__cvta_generic_to_shared(As + buf*128*ASTA);
        uint32_t bbase = (uint32_t)__cvta_generic_to_shared(Bs + buf*128*ASTB);
        #pragma unroll
        for (int i = 0; i < 4; i++) {
            int idx = tid + i*256;
            int r = idx >> 3, c4 = (idx & 7) * 4;
            cpa16(abase + (r*ASTA + c4)*4, A + (size_t)(bm + r)*K + k0 + c4);
            cpa16(bbase + (r*ASTB + c4)*4, W + (size_t)(bn + r)*K + k0 + c4);
        }
        asm volatile("cp.async.commit_group;\n");
    };

    load_tile(0, 0);

    int nkt = K / 32;
    for (int kt = 0; kt < nkt; kt++) {
        int cur = kt & 1;
        if (kt + 1 < nkt) {
            load_tile((kt + 1) * 32, (kt + 1) & 1);
            asm volatile("cp.async.wait_group 1;\n");
        } else {
            asm volatile("cp.async.wait_group 0;\n");
        }
        __syncthreads();

        const float* Ab = As + cur*128*ASTA;
        const float* Bb = Bs + cur*128*ASTB;
        #pragma unroll
        for (int ks = 0; ks < 4; ks++) {
            int kc = ks * 8;
            uint32_t a[4][4], b[4][2];
            #pragma unroll
            for (int mt = 0; mt < 4; mt++) {
                int r0 = warp_m + mt*16;
                if (QV) {
                    a[mt][0] = tf32u(Ab[(r0+g  )*ASTA + kc+tg  ]);
                    a[mt][1] = tf32u(Ab[(r0+g+8)*ASTA + kc+tg  ]);
                    a[mt][2] = tf32u(Ab[(r0+g  )*ASTA + kc+tg+4]);
                    a[mt][3] = tf32u(Ab[(r0+g+8)*ASTA + kc+tg+4]);
                } else {
                    float2 f0 = *(const float2*)&Ab[(r0+g  )*ASTA + kc + 2*tg];
                    float2 f1 = *(const float2*)&Ab[(r0+g+8)*ASTA + kc + 2*tg];
                    a[mt][0]=tf32u(f0.x); a[mt][2]=tf32u(f0.y);
                    a[mt][1]=tf32u(f1.x); a[mt][3]=tf32u(f1.y);
                }
            }
            #pragma unroll
            for (int nt = 0; nt < 4; nt++) {
                float2 fb = *(const float2*)&Bb[(warp_n+nt*8+g)*ASTB + kc + 2*tg];
                b[nt][0]=tf32u(fb.x); b[nt][1]=tf32u(fb.y);
            }
            #pragma unroll
            for (int mt = 0; mt < 4; mt++)
                #pragma unroll
                for (int nt = 0; nt < 4; nt++)
                    mma_tf32(acc[mt][nt], a[mt][0],a[mt][1],a[mt][2],a[mt][3],
                             b[nt][0], b[nt][1]);
        }
        __syncthreads();
    }

    if (!QV) {
        // natural-layout output (final projection)
        #pragma unroll
        for (int mt = 0; mt < 4; mt++) {
            int r0 = bm + warp_m + mt*16 + g;
            #pragma unroll
            for (int nt = 0; nt < 4; nt++) {
                int col = bn + warp_n + nt*8 + 2*tg;
                float bx2 = __ldg(bias + col), by = __ldg(bias + col + 1);
                float4 c = acc[mt][nt];
                *(float2*)(C + (size_t)r0*N + col)     = make_float2(c.x + bx2, c.y + by);
                *(float2*)(C + (size_t)(r0+8)*N + col) = make_float2(c.z + bx2, c.w + by);
            }
        }
    } else {
        // permuted-col output + per-head sorted row scatter
        int hsel = (bn + warp_n) >> 6;
        int pc = ((tg & 1) << 2) | (tg >> 1);   // physical slot of logical col 2tg
        #pragma unroll
        for (int mt = 0; mt < 4; mt++) {
            int r0 = bm + warp_m + mt*16 + g;
            int r1 = r0 + 8;
            int p0 = g_inv[(size_t)r0*HH + hsel];
            int p1 = g_inv[(size_t)r1*HH + hsel];
            size_t o0 = ((size_t)(r0 & ~(SS-1)) + p0) * (size_t)N;
            size_t o1 = ((size_t)(r1 & ~(SS-1)) + p1) * (size_t)N;
            #pragma unroll
            for (int nt = 0; nt < 4; nt++) {
                int colL = bn + warp_n + nt*8 + 2*tg;        // logical (bias)
                int colP = bn + warp_n + nt*8 + pc;          // physical (store)
                float bx2 = __ldg(bias + colL), by = __ldg(bias + colL + 1);
                float4 c = acc[mt][nt];
                C[o0 + colP]     = c.x + bx2;
                C[o0 + colP + 2] = c.y + by;
                C[o1 + colP]     = c.z + bx2;
                C[o1 + colP + 2] = c.w + by;
            }
        }
    }
}

// ---------------- 4) attention: permuted-k, float2 frags, 512 threads ----------------
#define SST 264   // mod 32 == 8
#define QST 72    // mod 32 == 8
#define VST 72

__global__ void __launch_bounds__(512) attn_kernel() {
    extern __shared__ float smem[];
    float* sS = smem;                    // 128 x SST (permuted cols)
    float* sQ = smem + 128*SST;          // 128 x QST
    float* sK = sQ + 128*QST;            // 128 x QST
    float* sV = sQ;                      // 256 x VST (reuses Q+K region)

    int tid = threadIdx.x;
    int lane = tid & 31, wid = tid >> 5;
    int g = lane >> 2, tg = lane & 3;
    int warp_m  = (wid & 7) * 16;
    int warp_nS = (wid >> 3) * 64;
    int warp_nV = (wid >> 3) * 32;

    int n = blockIdx.x, h = blockIdx.y, b = blockIdx.z;
    int base = n * BSZ;
    const float* qkp = g_qk + (size_t)b*SS*DD + h*DH;
    const float* vp  = g_v  + (size_t)b*SS*DD + h*DH;
    const float scale = 0.03125f;

    uint32_t sqb = (uint32_t)__cvta_generic_to_shared(sQ);
    uint32_t skb = (uint32_t)__cvta_generic_to_shared(sK);
    uint32_t svb = (uint32_t)__cvta_generic_to_shared(sV);

    for (int p = tid; p < 128*16; p += 512) {
        int r = p >> 4, seg = p & 15;
        cpa16(sqb + (r*QST + seg*4)*4, qkp + (size_t)(base + r)*DD + seg*4);
    }
    for (int p = tid; p < 128*16; p += 512) {
        int r = p >> 4, seg = p & 15;
        cpa16(skb + (r*QST + seg*4)*4, qkp + (size_t)((base + r) & (SS-1))*DD + seg*4);
    }
    asm volatile("cp.async.commit_group;\n");
    asm volatile("cp.async.wait_group 0;\n");
    __syncthreads();

    int pc = ((tg & 1) << 2) | (tg >> 1);

    #pragma unroll 1
    for (int hf = 0; hf < 2; hf++) {
        if (hf == 1) {
            __syncthreads();
            for (int p = tid; p < 128*16; p += 512) {
                int r = p >> 4, seg = p & 15;
                cpa16(skb + (r*QST + seg*4)*4,
                      qkp + (size_t)((base + 128 + r) & (SS-1))*DD + seg*4);
            }
            asm volatile("cp.async.commit_group;\n");
            asm volatile("cp.async.wait_group 0;\n");
            __syncthreads();
        }
        float4 acc[8];
        #pragma unroll
        for (int j = 0; j < 8; j++) acc[j] = make_float4(0.f,0.f,0.f,0.f);

        #pragma unroll
        for (int ks = 0; ks < 8; ks++) {
            int kc = ks * 8;
            uint32_t a[4], bfr[8][2];
            {
                float2 f0 = *(const float2*)&sQ[(warp_m+g  )*QST + kc + 2*tg];
                float2 f1 = *(const float2*)&sQ[(warp_m+g+8)*QST + kc + 2*tg];
                a[0]=tf32u(f0.x); a[2]=tf32u(f0.y);
                a[1]=tf32u(f1.x); a[3]=tf32u(f1.y);
            }
            #pragma unroll
            for (int nt = 0; nt < 8; nt++) {
                float2 fb = *(const float2*)&sK[(warp_nS+nt*8+g)*QST + kc + 2*tg];
                bfr[nt][0]=tf32u(fb.x); bfr[nt][1]=tf32u(fb.y);
            }
            #pragma unroll
            for (int nt = 0; nt < 8; nt++)
                mma_tf32(acc[nt], a[0],a[1],a[2],a[3], bfr[nt][0], bfr[nt][1]);
        }
        {
            int i0 = warp_m + g;
            #pragma unroll
            for (int nt = 0; nt < 8; nt++) {
                int jb = warp_nS + nt*8;
                int j0 = jb + 2*tg;                 // logical
                float4 c = acc[nt];
                float* p0 = sS + i0*SST + hf*128 + jb;
                float* p1 = p0 + 8*SST;
                if (hf == 0) {
                    p0[pc]   = (j0   == i0  ) ? -INFINITY : c.x*scale;
                    p0[pc+2] = (j0+1 == i0  ) ? -INFINITY : c.y*scale;
                    p1[pc]   = (j0   == i0+8) ? -INFINITY : c.z*scale;
                    p1[pc+2] = (j0+1 == i0+8) ? -INFINITY : c.w*scale;
                } else {
                    p0[pc]   = c.x*scale; p0[pc+2] = c.y*scale;
                    p1[pc]   = c.z*scale; p1[pc+2] = c.w*scale;
                }
            }
        }
    }
    __syncthreads();   // scores in sS; sQ/sK free

    // V load (overlaps softmax)
    for (int p = tid; p < 256*16; p += 512) {
        int j = p >> 4, seg = p & 15;
        cpa16(svb + (j*VST + seg*4)*4, vp + (size_t)((base + j) & (SS-1))*DD + seg*4);
    }
    asm volatile("cp.async.commit_group;\n");

    // softmax (quarter-row per thread; permutation is order-agnostic)
    {
        int row = tid >> 2, q = tid & 3;
        float* rp = sS + row*SST + q*64;
        float mx = -INFINITY;
        #pragma unroll 4
        for (int c = 0; c < 16; c++) {
            float4 v = ((float4*)rp)[c];
            mx = fmaxf(mx, fmaxf(fmaxf(v.x,v.y), fmaxf(v.z,v.w)));
        }
        mx = fmaxf(mx, __shfl_xor_sync(0xffffffffu, mx, 1));
        mx = fmaxf(mx, __shfl_xor_sync(0xffffffffu, mx, 2));
        float sum = 0.f;
        #pragma unroll 4
        for (int c = 0; c < 16; c++) {
            float4 v = ((float4*)rp)[c];
            v.x = __expf(v.x - mx); v.y = __expf(v.y - mx);
            v.z = __expf(v.z - mx); v.w = __expf(v.w - mx);
            sum += (v.x + v.y) + (v.z + v.w);
            ((float4*)rp)[c] = v;
        }
        sum += __shfl_xor_sync(0xffffffffu, sum, 1);
        sum += __shfl_xor_sync(0xffffffffu, sum, 2);
        float inv = 1.f / sum;
        #pragma unroll 4
        for (int c = 0; c < 16; c++) {
            float4 v = ((float4*)rp)[c];
            v.x = tf32r(v.x*inv); v.y = tf32r(v.y*inv);
            v.z = tf32r(v.z*inv); v.w = tf32r(v.w*inv);
            ((float4*)rp)[c] = v;
        }
    }
    asm volatile("cp.async.wait_group 0;\n");
    __syncthreads();

    // PV: out[128x64] = P[128x256] @ V[256x64]; A-frags float2 (permuted sS)
    float4 o[4];
    #pragma unroll
    for (int j = 0; j < 4; j++) o[j] = make_float4(0.f,0.f,0.f,0.f);

    #pragma unroll 4
    for (int ks = 0; ks < 32; ks++) {
        int kc = ks * 8;
        uint32_t a[4], bfr[4][2];
        {
            float2 f0 = *(const float2*)&sS[(warp_m+g  )*SST + kc + 2*tg];
            float2 f1 = *(const float2*)&sS[(warp_m+g+8)*SST + kc + 2*tg];
            a[0]=__float_as_uint(f0.x); a[2]=__float_as_uint(f0.y);
            a[1]=__float_as_uint(f1.x); a[3]=__float_as_uint(f1.y);
        }
        #pragma unroll
        for (int nt = 0; nt < 4; nt++) {
            int n0 = warp_nV + nt*8;
            bfr[nt][0] = tf32u(sV[(kc+tg  )*VST + n0+g]);
            bfr[nt][1] = tf32u(sV[(kc+tg+4)*VST + n0+g]);
        }
        #pragma unroll
        for (int nt = 0; nt < 4; nt++)
            mma_tf32(o[nt], a[0],a[1],a[2],a[3], bfr[nt][0], bfr[nt][1]);
    }

    // epilogue: cols are PHYSICAL (permuted) V features; store as-is — matches O-gemm
    float* outp = g_outs + (size_t)b*SS*DD + h*DH;
    {
        int i0 = warp_m + g;
        int t0 = base + i0;
        #pragma unroll
        for (int nt = 0; nt < 4; nt++) {
            int d0 = warp_nV + nt*8 + 2*tg;
            float4 c = o[nt];
            *(float2*)(outp + (size_t)t0*DD + d0)     = make_float2(c.x, c.y);
            *(float2*)(outp + (size_t)(t0+8)*DD + d0) = make_float2(c.z, c.w);
            if (d0 == 0) {   // physical 0 == logical feature 0
                g_ch0[((size_t)b*SS + t0  )*HH + h] = c.x;
                g_ch0[((size_t)b*SS + t0+8)*HH + h] = c.z;
            }
        }
    }
}

// ---------------- 5) feature-0-only inverse scatter (physical col 0 == logical 0) ----
__global__ void __launch_bounds__(256) scatter_kernel() {
    int i = blockIdx.x*256 + threadIdx.x;
    if (i >= BB*SS*HH) return;
    int h = i % HH;
    int b = i / (SS*HH);
    int p = g_idx[i];
    g_outs[((size_t)b*SS + p)*DD + h*DH] = g_ch0[i];
}

// ---------------- launch ----------------
extern "C" void kernel_launch(void* const* d_in, const int* in_sizes, int n_in,
                              void* d_out, int out_size) {
    const float* x  = (const float*)d_in[0];
    const float* Wh = (const float*)d_in[1];
    const float* Wq = (const float*)d_in[2];
    const float* bq = (const float*)d_in[3];
    const float* Wv = (const float*)d_in[4];
    const float* bv = (const float*)d_in[5];
    const float* Wo = (const float*)d_in[6];
    const float* bo = (const float*)d_in[7];
    float* out = (float*)d_out;

    float* qkp; cudaGetSymbolAddress((void**)&qkp, g_qk);
    float* vp;  cudaGetSymbolAddress((void**)&vp,  g_v);
    float* osp; cudaGetSymbolAddress((void**)&osp, g_outs);
    float* wqp; cudaGetSymbolAddress((void**)&wqp, g_wqp);
    float* wvp; cudaGetSymbolAddress((void**)&wvp, g_wvp);
    float* wop; cudaGetSymbolAddress((void**)&wop, g_wop);

    const int M = BB*SS;

    // 0) permute weights' k-dims within 8-groups (cheap: 4 MB each)
    int nw8 = (DD*DD)/8;
    perm8<<<(nw8+255)/256, 256>>>(Wq, wqp, nw8);
    perm8<<<(nw8+255)/256, 256>>>(Wv, wvp, nw8);
    perm8<<<(nw8+255)/256, 256>>>(Wo, wop, nw8);

    hash_kernel<<<M/32, dim3(32,32)>>>(x, Wh);
    sort_kernel<<<BB*HH, 1024>>>();

    size_t gsmemQV = (size_t)(2*128*36 + 2*128*ASTB) * sizeof(float);  // 77,824 B
    size_t gsmemO  = (size_t)(2*128*40 + 2*128*ASTB) * sizeof(float);  // 81,920 B
    cudaFuncSetAttribute(gemm3<true>,  cudaFuncAttributeMaxDynamicSharedMemorySize, (int)gsmemQV);
    cudaFuncSetAttribute(gemm3<false>, cudaFuncAttributeMaxDynamicSharedMemorySize, (int)gsmemO);

    // QV projection: A = x (natural), B = permuted weights; epilogue sorts rows + permutes cols
    gemm3<true><<<dim3(16, M/128), 256, gsmemQV>>>(x, wqp, bq, qkp, wvp, bv, vp, 8, DD, DD);

    size_t asmem = (size_t)(128*SST + 2*128*QST) * sizeof(float);  // 208,896 B
    cudaFuncSetAttribute(attn_kernel, cudaFuncAttributeMaxDynamicSharedMemorySize, (int)asmem);
    dim3 ag(NB, HH, BB);
    attn_kernel<<<ag, 512, asmem>>>();

    scatter_kernel<<<(BB*SS*HH + 255)/256, 256>>>();

    // O projection: A = g_outs (permuted), B = permuted Wo; natural output
    gemm3<false><<<dim3(8, M/128), 256, gsmemO>>>(osp, wop, bo, out, wop, bo, out, 8, DD, DD);
}

// round 12
// speedup vs baseline: 1.1207x; 1.0794x over previous
#include <cuda_runtime.h>
#include <math.h>
#include <stdint.h>

#define BB 4
#define SS 4096
#define DD 1024
#define HH 16
#define DH 64
#define BSZ 128
#define NB 32
#define EPSF 1e-4f

// ---------------- scratch ----------------
__device__ float g_angles[BB*SS*HH];
__device__ int   g_idx[BB*SS*HH];
__device__ int   g_inv[BB*SS*HH];
__device__ float g_qk[(size_t)BB*SS*DD];    // SORTED per head: [b, pos, h, d]
__device__ float g_v [(size_t)BB*SS*DD];    // SORTED per head
__device__ float g_outs[(size_t)BB*SS*DD];
__device__ float g_ch0[BB*SS*HH];

__device__ __forceinline__ float tf32r(float x) {
    uint32_t u;
    asm("cvt.rna.tf32.f32 %0, %1;" : "=r"(u) : "f"(x));
    return __uint_as_float(u);
}
__device__ __forceinline__ uint32_t tf32u(float x) {
    uint32_t u;
    asm("cvt.rna.tf32.f32 %0, %1;" : "=r"(u) : "f"(x));
    return u;
}

__device__ __forceinline__ void mma_tf32(float4& d,
                                         uint32_t a0, uint32_t a1, uint32_t a2, uint32_t a3,
                                         uint32_t b0, uint32_t b1) {
    asm volatile(
        "mma.sync.aligned.m16n8k8.row.col.f32.tf32.tf32.f32 "
        "{%0,%1,%2,%3},{%4,%5,%6,%7},{%8,%9},{%0,%1,%2,%3};"
        : "+f"(d.x), "+f"(d.y), "+f"(d.z), "+f"(d.w)
        : "r"(a0), "r"(a1), "r"(a2), "r"(a3), "r"(b0), "r"(b1));
}

__device__ __forceinline__ void cpa16(uint32_t saddr, const float* g) {
    asm volatile("cp.async.cg.shared.global [%0], [%1], 16;\n" :: "r"(saddr), "l"(g));
}

// ---------------- 1) hash v2: 4 outputs/thread, float4 swizzled x, serial chains ----
// Chain per (token,output) is BIT-IDENTICAL to v1: single fp32 acc, k ascending.
__global__ void __launch_bounds__(256) hash_kernel(const float* __restrict__ x,
                                                   const float* __restrict__ Wh) {
    __shared__ float4 xs4[32][64];     // one 256-float k-chunk per token, XOR-swizzled
    __shared__ float  hs[32][33];
    int tid = threadIdx.x;
    int g  = tid & 31;                 // token in group
    int o0 = (tid >> 5) * 4;           // first of 4 outputs
    int tok0 = blockIdx.x * 32;
    const float4* xbase = (const float4*)(x + (size_t)tok0 * DD);
    const float4* w4 = (const float4*)Wh;

    float acc0 = 0.f, acc1 = 0.f, acc2 = 0.f, acc3 = 0.f;
    for (int c = 0; c < 4; c++) {
        __syncthreads();
        #pragma unroll
        for (int i = 0; i < 8; i++) {
            int idx = tid + i*256;
            int r = idx >> 6, k4 = idx & 63;
            xs4[r][k4 ^ (r & 7)] = xbase[(size_t)r*(DD/4) + c*64 + k4];
        }
        __syncthreads();
        const float4* wr0 = w4 + (size_t)(o0+0)*(DD/4) + c*64;
        const float4* wr1 = w4 + (size_t)(o0+1)*(DD/4) + c*64;
        const float4* wr2 = w4 + (size_t)(o0+2)*(DD/4) + c*64;
        const float4* wr3 = w4 + (size_t)(o0+3)*(DD/4) + c*64;
        #pragma unroll 8
        for (int k4 = 0; k4 < 64; k4++) {
            float4 xv = xs4[g][k4 ^ (g & 7)];
            float4 w0 = __ldg(wr0 + k4);
            float4 w1 = __ldg(wr1 + k4);
            float4 w2 = __ldg(wr2 + k4);
            float4 w3 = __ldg(wr3 + k4);
            acc0 = fmaf(xv.x, w0.x, acc0); acc0 = fmaf(xv.y, w0.y, acc0);
            acc0 = fmaf(xv.z, w0.z, acc0); acc0 = fmaf(xv.w, w0.w, acc0);
            acc1 = fmaf(xv.x, w1.x, acc1); acc1 = fmaf(xv.y, w1.y, acc1);
            acc1 = fmaf(xv.z, w1.z, acc1); acc1 = fmaf(xv.w, w1.w, acc1);
            acc2 = fmaf(xv.x, w2.x, acc2); acc2 = fmaf(xv.y, w2.y, acc2);
            acc2 = fmaf(xv.z, w2.z, acc2); acc2 = fmaf(xv.w, w2.w, acc2);
            acc3 = fmaf(xv.x, w3.x, acc3); acc3 = fmaf(xv.y, w3.y, acc3);
            acc3 = fmaf(xv.z, w3.z, acc3); acc3 = fmaf(xv.w, w3.w, acc3);
        }
    }
    hs[g][o0]   = acc0;
    hs[g][o0+1] = acc1;
    hs[g][o0+2] = acc2;
    hs[g][o0+3] = acc3;
    __syncthreads();
    for (int i = tid; i < 32*HH; i += 256) {
        int gg = i >> 4, hh = i & 15;
        float h0 = hs[gg][2*hh], h1 = hs[gg][2*hh+1];
        g_angles[(size_t)(tok0 + gg)*HH + hh] = __fdiv_rn(h0, h1 + EPSF);
    }
}

// ---------------- 2) STABLE bitonic argsort + inverse ----------------
__global__ void __launch_bounds__(1024) sort_kernel() {
    int b = blockIdx.x / HH, h = blockIdx.x % HH;
    __shared__ float key[SS];
    __shared__ int   val[SS];
    int tid = threadIdx.x;
    for (int i = tid; i < SS; i += 1024) {
        key[i] = g_angles[((size_t)b*SS + i)*HH + h];
        val[i] = i;
    }
    __syncthreads();
    for (int k = 2; k <= SS; k <<= 1) {
        for (int j = k >> 1; j > 0; j >>= 1) {
            for (int i = tid; i < SS; i += 1024) {
                int ixj = i ^ j;
                if (ixj > i) {
                    bool up = ((i & k) == 0);
                    float ki = key[i], kj = key[ixj];
                    int   vi = val[i], vj = val[ixj];
                    bool gt = (ki > kj) || (ki == kj && vi > vj);
                    if (gt == up) {
                        key[i] = kj; key[ixj] = ki;
                        val[i] = vj; val[ixj] = vi;
                    }
                }
            }
            __syncthreads();
        }
    }
    for (int i = tid; i < SS; i += 1024) {
        int v = val[i];
        g_idx[((size_t)b*SS + i)*HH + h] = v;
        g_inv[((size_t)b*SS + v)*HH + h] = i;
    }
}

// ---------------- 3) TF32 GEMM: 128x128x32, 2-stage cp.async, 2 blocks/SM ----
#define AST 36

__global__ void __launch_bounds__(256, 2) gemm3(const float* __restrict__ A,
                                                const float* __restrict__ W0,
                                                const float* __restrict__ b0,
                                                float* __restrict__ C0,
                                                const float* __restrict__ W1,
                                                const float* __restrict__ b1,
                                                float* __restrict__ C1,
                                                int split, int N, int K, int mode) {
    extern __shared__ float smem[];
    float* As = smem;                        // [2][128][AST]
    float* Bs = smem + 2*128*AST;            // [2][128][AST]

    const float* W; const float* bias; float* C;
    int bx = blockIdx.x;
    if (bx < split) { W = W0; bias = b0; C = C0; }
    else            { W = W1; bias = b1; C = C1; bx -= split; }
    int bm = blockIdx.y * 128, bn = bx * 128;

    int tid  = threadIdx.x;
    int lane = tid & 31, wid = tid >> 5;
    int g = lane >> 2, tg = lane & 3;
    int warp_m = (wid & 1) * 64;
    int warp_n = (wid >> 1) * 32;

    float4 acc[4][4];
    #pragma unroll
    for (int i = 0; i < 4; i++)
        #pragma unroll
        for (int j = 0; j < 4; j++) acc[i][j] = make_float4(0.f,0.f,0.f,0.f);

    auto load_tile = [&](int k0, int buf) {
        uint32_t abase = (uint32_t)__cvta_generic_to_shared(As + buf*128*AST);
        uint32_t bbase = (uint32_t)__cvta_generic_to_shared(Bs + buf*128*AST);
        #pragma unroll
        for (int i = 0; i < 4; i++) {
            int idx = tid + i*256;
            int r = idx >> 3, c4 = (idx & 7) * 4;
            cpa16(abase + (r*AST + c4)*4, A + (size_t)(bm + r)*K + k0 + c4);
            cpa16(bbase + (r*AST + c4)*4, W + (size_t)(bn + r)*K + k0 + c4);
        }
        asm volatile("cp.async.commit_group;\n");
    };

    load_tile(0, 0);

    int nkt = K / 32;
    for (int kt = 0; kt < nkt; kt++) {
        int cur = kt & 1;
        if (kt + 1 < nkt) {
            load_tile((kt + 1) * 32, (kt + 1) & 1);
            asm volatile("cp.async.wait_group 1;\n");
        } else {
            asm volatile("cp.async.wait_group 0;\n");
        }
        __syncthreads();

        const float* Ab = As + cur*128*AST;
        const float* Bb = Bs + cur*128*AST;
        #pragma unroll
        for (int ks = 0; ks < 4; ks++) {
            int kc = ks * 8;
            uint32_t a[4][4], b[4][2];
            #pragma unroll
            for (int mt = 0; mt < 4; mt++) {
                int r0 = warp_m + mt*16;
                a[mt][0] = tf32u(Ab[(r0+g  )*AST + kc+tg  ]);
                a[mt][1] = tf32u(Ab[(r0+g+8)*AST + kc+tg  ]);
                a[mt][2] = tf32u(Ab[(r0+g  )*AST + kc+tg+4]);
                a[mt][3] = tf32u(Ab[(r0+g+8)*AST + kc+tg+4]);
            }
            #pragma unroll
            for (int nt = 0; nt < 4; nt++) {
                int n0 = warp_n + nt*8;
                b[nt][0] = tf32u(Bb[(n0+g)*AST + kc+tg  ]);
                b[nt][1] = tf32u(Bb[(n0+g)*AST + kc+tg+4]);
            }
            #pragma unroll
            for (int mt = 0; mt < 4; mt++)
                #pragma unroll
                for (int nt = 0; nt < 4; nt++)
                    mma_tf32(acc[mt][nt], a[mt][0],a[mt][1],a[mt][2],a[mt][3],
                             b[nt][0], b[nt][1]);
        }
        __syncthreads();
    }

    if (mode == 0) {
        #pragma unroll
        for (int mt = 0; mt < 4; mt++) {
            int r0 = bm + warp_m + mt*16 + g;
            #pragma unroll
            for (int nt = 0; nt < 4; nt++) {
                int col = bn + warp_n + nt*8 + 2*tg;
                float bx2 = __ldg(bias + col), by = __ldg(bias + col + 1);
                float4 c = acc[mt][nt];
                *(float2*)(C + (size_t)r0*N + col)     = make_float2(c.x + bx2, c.y + by);
                *(float2*)(C + (size_t)(r0+8)*N + col) = make_float2(c.z + bx2, c.w + by);
            }
        }
    } else {
        // scatter rows into per-head sorted order via inverse permutation
        int hsel = (bn + warp_n) >> 6;
        #pragma unroll
        for (int mt = 0; mt < 4; mt++) {
            int r0 = bm + warp_m + mt*16 + g;
            int r1 = r0 + 8;
            int p0 = g_inv[(size_t)r0*HH + hsel];
            int p1 = g_inv[(size_t)r1*HH + hsel];
            size_t o0 = ((size_t)(r0 & ~(SS-1)) + p0) * (size_t)N;
            size_t o1 = ((size_t)(r1 & ~(SS-1)) + p1) * (size_t)N;
            #pragma unroll
            for (int nt = 0; nt < 4; nt++) {
                int col = bn + warp_n + nt*8 + 2*tg;
                float bx2 = __ldg(bias + col), by = __ldg(bias + col + 1);
                float4 c = acc[mt][nt];
                *(float2*)(C + o0 + col) = make_float2(c.x + bx2, c.y + by);
                *(float2*)(C + o1 + col) = make_float2(c.z + bx2, c.w + by);
            }
        }
    }
}

// ---------------- 4) attention: sorted inputs, cp.async, 512 threads ----------------
#define SST 260
#define QST 68
#define VST 72   // 8*tg+g bank pattern -> conflict-free PV B-frags

__global__ void __launch_bounds__(512) attn_kernel() {
    extern __shared__ float smem[];
    float* sS = smem;                    // 128 x SST
    float* sQ = smem + 128*SST;          // 128 x QST
    float* sK = sQ + 128*QST;            // 128 x QST
    float* sV = sQ;                      // 256 x VST (reuses Q/K + tail)

    int tid = threadIdx.x;
    int lane = tid & 31, wid = tid >> 5;
    int g = lane >> 2, tg = lane & 3;
    int warp_m  = (wid & 7) * 16;
    int warp_nS = (wid >> 3) * 64;
    int warp_nV = (wid >> 3) * 32;

    int n = blockIdx.x, h = blockIdx.y, b = blockIdx.z;
    int base = n * BSZ;
    const float* qkp = g_qk + (size_t)b*SS*DD + h*DH;   // sorted rows
    const float* vp  = g_v  + (size_t)b*SS*DD + h*DH;
    const float scale = 0.03125f;

    uint32_t sqb = (uint32_t)__cvta_generic_to_shared(sQ);
    uint32_t skb = (uint32_t)__cvta_generic_to_shared(sK);
    uint32_t svb = (uint32_t)__cvta_generic_to_shared(sV);

    for (int p = tid; p < 128*16; p += 512) {
        int r = p >> 4, seg = p & 15;
        cpa16(sqb + (r*QST + seg*4)*4, qkp + (size_t)(base + r)*DD + seg*4);
    }
    for (int p = tid; p < 128*16; p += 512) {
        int r = p >> 4, seg = p & 15;
        cpa16(skb + (r*QST + seg*4)*4, qkp + (size_t)((base + r) & (SS-1))*DD + seg*4);
    }
    asm volatile("cp.async.commit_group;\n");
    asm volatile("cp.async.wait_group 0;\n");
    __syncthreads();

    #pragma unroll 1
    for (int hf = 0; hf < 2; hf++) {
        if (hf == 1) {
            __syncthreads();   // all done reading K half0
            for (int p = tid; p < 128*16; p += 512) {
                int r = p >> 4, seg = p & 15;
                cpa16(skb + (r*QST + seg*4)*4,
                      qkp + (size_t)((base + 128 + r) & (SS-1))*DD + seg*4);
            }
            asm volatile("cp.async.commit_group;\n");
            asm volatile("cp.async.wait_group 0;\n");
            __syncthreads();
        }
        float4 acc[8];
        #pragma unroll
        for (int j = 0; j < 8; j++) acc[j] = make_float4(0.f,0.f,0.f,0.f);

        #pragma unroll
        for (int ks = 0; ks < 8; ks++) {
            int kc = ks * 8;
            uint32_t a[4], bfr[8][2];
            a[0] = tf32u(sQ[(warp_m+g  )*QST + kc+tg  ]);
            a[1] = tf32u(sQ[(warp_m+g+8)*QST + kc+tg  ]);
            a[2] = tf32u(sQ[(warp_m+g  )*QST + kc+tg+4]);
            a[3] = tf32u(sQ[(warp_m+g+8)*QST + kc+tg+4]);
            #pragma unroll
            for (int nt = 0; nt < 8; nt++) {
                int n0 = warp_nS + nt*8;
                bfr[nt][0] = tf32u(sK[(n0+g)*QST + kc+tg  ]);
                bfr[nt][1] = tf32u(sK[(n0+g)*QST + kc+tg+4]);
            }
            #pragma unroll
            for (int nt = 0; nt < 8; nt++)
                mma_tf32(acc[nt], a[0],a[1],a[2],a[3], bfr[nt][0], bfr[nt][1]);
        }
        {
            int i0 = warp_m + g;
            #pragma unroll
            for (int nt = 0; nt < 8; nt++) {
                int j0 = warp_nS + nt*8 + 2*tg;
                float4 c = acc[nt];
                float* p0 = sS + i0*SST + hf*128 + j0;
                float* p1 = p0 + 8*SST;
                if (hf == 0) {
                    p0[0] = (j0   == i0  ) ? -INFINITY : c.x*scale;
                    p0[1] = (j0+1 == i0  ) ? -INFINITY : c.y*scale;
                    p1[0] = (j0   == i0+8) ? -INFINITY : c.z*scale;
                    p1[1] = (j0+1 == i0+8) ? -INFINITY : c.w*scale;
                } else {
                    p0[0] = c.x*scale; p0[1] = c.y*scale;
                    p1[0] = c.z*scale; p1[1] = c.w*scale;
                }
            }
        }
    }
    __syncthreads();   // scores in sS; sQ/sK free

    // V load (overlaps softmax)
    for (int p = tid; p < 256*16; p += 512) {
        int j = p >> 4, seg = p & 15;
        cpa16(svb + (j*VST + seg*4)*4, vp + (size_t)((base + j) & (SS-1))*DD + seg*4);
    }
    asm volatile("cp.async.commit_group;\n");

    // softmax (quarter-row per thread)
    {
        int row = tid >> 2, q = tid & 3;
        float* rp = sS + row*SST + q*64;
        float mx = -INFINITY;
        #pragma unroll 4
        for (int c = 0; c < 16; c++) {
            float4 v = ((float4*)rp)[c];
            mx = fmaxf(mx, fmaxf(fmaxf(v.x,v.y), fmaxf(v.z,v.w)));
        }
        mx = fmaxf(mx, __shfl_xor_sync(0xffffffffu, mx, 1));
        mx = fmaxf(mx, __shfl_xor_sync(0xffffffffu, mx, 2));
        float sum = 0.f;
        #pragma unroll 4
        for (int c = 0; c < 16; c++) {
            float4 v = ((float4*)rp)[c];
            v.x = __expf(v.x - mx); v.y = __expf(v.y - mx);
            v.z = __expf(v.z - mx); v.w = __expf(v.w - mx);
            sum += (v.x + v.y) + (v.z + v.w);
            ((float4*)rp)[c] = v;
        }
        sum += __shfl_xor_sync(0xffffffffu, sum, 1);
        sum += __shfl_xor_sync(0xffffffffu, sum, 2);
        float inv = 1.f / sum;
        #pragma unroll 4
        for (int c = 0; c < 16; c++) {
            float4 v = ((float4*)rp)[c];
            v.x = tf32r(v.x*inv); v.y = tf32r(v.y*inv);
            v.z = tf32r(v.z*inv); v.w = tf32r(v.w*inv);
            ((float4*)rp)[c] = v;
        }
    }
    asm volatile("cp.async.wait_group 0;\n");
    __syncthreads();

    // PV: out[128x64] = P[128x256] @ V[256x64] (V k-major: natural B operand)
    float4 o[4];
    #pragma unroll
    for (int j = 0; j < 4; j++) o[j] = make_float4(0.f,0.f,0.f,0.f);

    #pragma unroll 4
    for (int ks = 0; ks < 32; ks++) {
        int kc = ks * 8;
        uint32_t a[4], bfr[4][2];
        a[0] = __float_as_uint(sS[(warp_m+g  )*SST + kc+tg  ]);
        a[1] = __float_as_uint(sS[(warp_m+g+8)*SST + kc+tg  ]);
        a[2] = __float_as_uint(sS[(warp_m+g  )*SST + kc+tg+4]);
        a[3] = __float_as_uint(sS[(warp_m+g+8)*SST + kc+tg+4]);
        #pragma unroll
        for (int nt = 0; nt < 4; nt++) {
            int n0 = warp_nV + nt*8;
            bfr[nt][0] = tf32u(sV[(kc+tg  )*VST + n0+g]);
            bfr[nt][1] = tf32u(sV[(kc+tg+4)*VST + n0+g]);
        }
        #pragma unroll
        for (int nt = 0; nt < 4; nt++)
            mma_tf32(o[nt], a[0],a[1],a[2],a[3], bfr[nt][0], bfr[nt][1]);
    }

    float* outp = g_outs + (size_t)b*SS*DD + h*DH;
    {
        int i0 = warp_m + g;
        int t0 = base + i0;
        #pragma unroll
        for (int nt = 0; nt < 4; nt++) {
            int d0 = warp_nV + nt*8 + 2*tg;
            float4 c = o[nt];
            *(float2*)(outp + (size_t)t0*DD + d0)     = make_float2(c.x, c.y);
            *(float2*)(outp + (size_t)(t0+8)*DD + d0) = make_float2(c.z, c.w);
            if (d0 == 0) {
                g_ch0[((size_t)b*SS + t0  )*HH + h] = c.x;
                g_ch0[((size_t)b*SS + t0+8)*HH + h] = c.z;
            }
        }
    }
}

// ---------------- 5) feature-0-only inverse scatter ----------------
__global__ void __launch_bounds__(256) scatter_kernel() {
    int i = blockIdx.x*256 + threadIdx.x;
    if (i >= BB*SS*HH) return;
    int h = i % HH;
    int b = i / (SS*HH);
    int p = g_idx[i];
    g_outs[((size_t)b*SS + p)*DD + h*DH] = g_ch0[i];
}

// ---------------- launch ----------------
extern "C" void kernel_launch(void* const* d_in, const int* in_sizes, int n_in,
                              void* d_out, int out_size) {
    const float* x  = (const float*)d_in[0];
    const float* Wh = (const float*)d_in[1];
    const float* Wq = (const float*)d_in[2];
    const float* bq = (const float*)d_in[3];
    const float* Wv = (const float*)d_in[4];
    const float* bv = (const float*)d_in[5];
    const float* Wo = (const float*)d_in[6];
    const float* bo = (const float*)d_in[7];
    float* out = (float*)d_out;

    float* qkp; cudaGetSymbolAddress((void**)&qkp, g_qk);
    float* vp;  cudaGetSymbolAddress((void**)&vp,  g_v);
    float* osp; cudaGetSymbolAddress((void**)&osp, g_outs);

    const int M = BB*SS;

    hash_kernel<<<M/32, 256>>>(x, Wh);
    sort_kernel<<<BB*HH, 1024>>>();

    size_t gsmem = (size_t)(4*128*AST) * sizeof(float);   // 73,728 B (2 stages A+B)
    cudaFuncSetAttribute(gemm3, cudaFuncAttributeMaxDynamicSharedMemorySize, (int)gsmem);
    // fused Q/V projection, rows scattered into per-head sorted order
    gemm3<<<dim3(16, M/128), 256, gsmem>>>(x, Wq, bq, qkp, Wv, bv, vp, 8, DD, DD, 1);

    size_t asmem = (size_t)(128*SST + 2*128*QST + 1024) * sizeof(float);  // 206,848 B
    cudaFuncSetAttribute(attn_kernel, cudaFuncAttributeMaxDynamicSharedMemorySize, (int)asmem);
    dim3 ag(NB, HH, BB);
    attn_kernel<<<ag, 512, asmem>>>();

    scatter_kernel<<<(BB*SS*HH + 255)/256, 256>>>();
    gemm3<<<dim3(8, M/128), 256, gsmem>>>(osp, Wo, bo, out, Wo, bo, out, 8, DD, DD, 0);
}

// round 14
// speedup vs baseline: 1.1291x; 1.0076x over previous
#include <cuda_runtime.h>
#include <math.h>
#include <stdint.h>

#define BB 4
#define SS 4096
#define DD 1024
#define HH 16
#define DH 64
#define BSZ 128
#define NB 32
#define EPSF 1e-4f

// ---------------- scratch ----------------
__device__ float g_angles[BB*SS*HH];
__device__ int   g_idx[BB*SS*HH];
__device__ int   g_inv[BB*SS*HH];
__device__ float g_qk[(size_t)BB*SS*DD];    // SORTED per head
__device__ float g_v [(size_t)BB*SS*DD];    // SORTED per head
__device__ float g_outs[(size_t)BB*SS*DD];
__device__ float g_ch0[BB*SS*HH];

__device__ __forceinline__ float tf32r(float x) {
    uint32_t u;
    asm("cvt.rna.tf32.f32 %0, %1;" : "=r"(u) : "f"(x));
    return __uint_as_float(u);
}
__device__ __forceinline__ uint32_t tf32u(float x) {
    uint32_t u;
    asm("cvt.rna.tf32.f32 %0, %1;" : "=r"(u) : "f"(x));
    return u;
}

__device__ __forceinline__ void mma_tf32(float4& d,
                                         uint32_t a0, uint32_t a1, uint32_t a2, uint32_t a3,
                                         uint32_t b0, uint32_t b1) {
    asm volatile(
        "mma.sync.aligned.m16n8k8.row.col.f32.tf32.tf32.f32 "
        "{%0,%1,%2,%3},{%4,%5,%6,%7},{%8,%9},{%0,%1,%2,%3};"
        : "+f"(d.x), "+f"(d.y), "+f"(d.z), "+f"(d.w)
        : "r"(a0), "r"(a1), "r"(a2), "r"(a3), "r"(b0), "r"(b1));
}

__device__ __forceinline__ void cpa16(uint32_t saddr, const float* g) {
    asm volatile("cp.async.cg.shared.global [%0], [%1], 16;\n" :: "r"(saddr), "l"(g));
}

// ---------------- 1) hash v2 (bit-identical chains) ----------------
__global__ void __launch_bounds__(256) hash_kernel(const float* __restrict__ x,
                                                   const float* __restrict__ Wh) {
    __shared__ float4 xs4[32][64];
    __shared__ float  hs[32][33];
    int tid = threadIdx.x;
    int g  = tid & 31;
    int o0 = (tid >> 5) * 4;
    int tok0 = blockIdx.x * 32;
    const float4* xbase = (const float4*)(x + (size_t)tok0 * DD);
    const float4* w4 = (const float4*)Wh;

    float acc0 = 0.f, acc1 = 0.f, acc2 = 0.f, acc3 = 0.f;
    for (int c = 0; c < 4; c++) {
        __syncthreads();
        #pragma unroll
        for (int i = 0; i < 8; i++) {
            int idx = tid + i*256;
            int r = idx >> 6, k4 = idx & 63;
            xs4[r][k4 ^ (r & 7)] = xbase[(size_t)r*(DD/4) + c*64 + k4];
        }
        __syncthreads();
        const float4* wr0 = w4 + (size_t)(o0+0)*(DD/4) + c*64;
        const float4* wr1 = w4 + (size_t)(o0+1)*(DD/4) + c*64;
        const float4* wr2 = w4 + (size_t)(o0+2)*(DD/4) + c*64;
        const float4* wr3 = w4 + (size_t)(o0+3)*(DD/4) + c*64;
        #pragma unroll 8
        for (int k4 = 0; k4 < 64; k4++) {
            float4 xv = xs4[g][k4 ^ (g & 7)];
            float4 w0 = __ldg(wr0 + k4);
            float4 w1 = __ldg(wr1 + k4);
            float4 w2 = __ldg(wr2 + k4);
            float4 w3 = __ldg(wr3 + k4);
            acc0 = fmaf(xv.x, w0.x, acc0); acc0 = fmaf(xv.y, w0.y, acc0);
            acc0 = fmaf(xv.z, w0.z, acc0); acc0 = fmaf(xv.w, w0.w, acc0);
            acc1 = fmaf(xv.x, w1.x, acc1); acc1 = fmaf(xv.y, w1.y, acc1);
            acc1 = fmaf(xv.z, w1.z, acc1); acc1 = fmaf(xv.w, w1.w, acc1);
            acc2 = fmaf(xv.x, w2.x, acc2); acc2 = fmaf(xv.y, w2.y, acc2);
            acc2 = fmaf(xv.z, w2.z, acc2); acc2 = fmaf(xv.w, w2.w, acc2);
            acc3 = fmaf(xv.x, w3.x, acc3); acc3 = fmaf(xv.y, w3.y, acc3);
            acc3 = fmaf(xv.z, w3.z, acc3); acc3 = fmaf(xv.w, w3.w, acc3);
        }
    }
    hs[g][o0]   = acc0;
    hs[g][o0+1] = acc1;
    hs[g][o0+2] = acc2;
    hs[g][o0+3] = acc3;
    __syncthreads();
    for (int i = tid; i < 32*HH; i += 256) {
        int gg = i >> 4, hh = i & 15;
        float h0 = hs[gg][2*hh], h1 = hs[gg][2*hh+1];
        g_angles[(size_t)(tok0 + gg)*HH + hh] = __fdiv_rn(h0, h1 + EPSF);
    }
}

// ---------------- 2) STABLE bitonic argsort + inverse ----------------
__global__ void __launch_bounds__(1024) sort_kernel() {
    int b = blockIdx.x / HH, h = blockIdx.x % HH;
    __shared__ float key[SS];
    __shared__ int   val[SS];
    int tid = threadIdx.x;
    for (int i = tid; i < SS; i += 1024) {
        key[i] = g_angles[((size_t)b*SS + i)*HH + h];
        val[i] = i;
    }
    __syncthreads();
    for (int k = 2; k <= SS; k <<= 1) {
        for (int j = k >> 1; j > 0; j >>= 1) {
            for (int i = tid; i < SS; i += 1024) {
                int ixj = i ^ j;
                if (ixj > i) {
                    bool up = ((i & k) == 0);
                    float ki = key[i], kj = key[ixj];
                    int   vi = val[i], vj = val[ixj];
                    bool gt = (ki > kj) || (ki == kj && vi > vj);
                    if (gt == up) {
                        key[i] = kj; key[ixj] = ki;
                        val[i] = vj; val[ixj] = vi;
                    }
                }
            }
            __syncthreads();
        }
    }
    for (int i = tid; i < SS; i += 1024) {
        int v = val[i];
        g_idx[((size_t)b*SS + i)*HH + h] = v;
        g_inv[((size_t)b*SS + v)*HH + h] = i;
    }
}

// ---------------- 3) TF32 GEMM: 128x128x32, 2-stage cp.async, 2 blocks/SM ----
#define AST 36

__global__ void __launch_bounds__(256, 2) gemm3(const float* __restrict__ A,
                                                const float* __restrict__ W0,
                                                const float* __restrict__ b0,
                                                float* __restrict__ C0,
                                                const float* __restrict__ W1,
                                                const float* __restrict__ b1,
                                                float* __restrict__ C1,
                                                int split, int N, int K, int mode) {
    extern __shared__ float smem[];
    float* As = smem;
    float* Bs = smem + 2*128*AST;

    const float* W; const float* bias; float* C;
    int bx = blockIdx.x;
    if (bx < split) { W = W0; bias = b0; C = C0; }
    else            { W = W1; bias = b1; C = C1; bx -= split; }
    int bm = blockIdx.y * 128, bn = bx * 128;

    int tid  = threadIdx.x;
    int lane = tid & 31, wid = tid >> 5;
    int g = lane >> 2, tg = lane & 3;
    int warp_m = (wid & 1) * 64;
    int warp_n = (wid >> 1) * 32;

    float4 acc[4][4];
    #pragma unroll
    for (int i = 0; i < 4; i++)
        #pragma unroll
        for (int j = 0; j < 4; j++) acc[i][j] = make_float4(0.f,0.f,0.f,0.f);

    auto load_tile = [&](int k0, int buf) {
        uint32_t abase = (uint32_t)__cvta_generic_to_shared(As + buf*128*AST);
        uint32_t bbase = (uint32_t)__cvta_generic_to_shared(Bs + buf*128*AST);
        #pragma unroll
        for (int i = 0; i < 4; i++) {
            int idx = tid + i*256;
            int r = idx >> 3, c4 = (idx & 7) * 4;
            cpa16(abase + (r*AST + c4)*4, A + (size_t)(bm + r)*K + k0 + c4);
            cpa16(bbase + (r*AST + c4)*4, W + (size_t)(bn + r)*K + k0 + c4);
        }
        asm volatile("cp.async.commit_group;\n");
    };

    load_tile(0, 0);

    int nkt = K / 32;
    for (int kt = 0; kt < nkt; kt++) {
        int cur = kt & 1;
        if (kt + 1 < nkt) {
            load_tile((kt + 1) * 32, (kt + 1) & 1);
            asm volatile("cp.async.wait_group 1;\n");
        } else {
            asm volatile("cp.async.wait_group 0;\n");
        }
        __syncthreads();

        const float* Ab = As + cur*128*AST;
        const float* Bb = Bs + cur*128*AST;
        #pragma unroll
        for (int ks = 0; ks < 4; ks++) {
            int kc = ks * 8;
            uint32_t a[4][4], b[4][2];
            #pragma unroll
            for (int mt = 0; mt < 4; mt++) {
                int r0 = warp_m + mt*16;
                a[mt][0] = tf32u(Ab[(r0+g  )*AST + kc+tg  ]);
                a[mt][1] = tf32u(Ab[(r0+g+8)*AST + kc+tg  ]);
                a[mt][2] = tf32u(Ab[(r0+g  )*AST + kc+tg+4]);
                a[mt][3] = tf32u(Ab[(r0+g+8)*AST + kc+tg+4]);
            }
            #pragma unroll
            for (int nt = 0; nt < 4; nt++) {
                int n0 = warp_n + nt*8;
                b[nt][0] = tf32u(Bb[(n0+g)*AST + kc+tg  ]);
                b[nt][1] = tf32u(Bb[(n0+g)*AST + kc+tg+4]);
            }
            #pragma unroll
            for (int mt = 0; mt < 4; mt++)
                #pragma unroll
                for (int nt = 0; nt < 4; nt++)
                    mma_tf32(acc[mt][nt], a[mt][0],a[mt][1],a[mt][2],a[mt][3],
                             b[nt][0], b[nt][1]);
        }
        __syncthreads();
    }

    if (mode == 0) {
        #pragma unroll
        for (int mt = 0; mt < 4; mt++) {
            int r0 = bm + warp_m + mt*16 + g;
            #pragma unroll
            for (int nt = 0; nt < 4; nt++) {
                int col = bn + warp_n + nt*8 + 2*tg;
                float bx2 = __ldg(bias + col), by = __ldg(bias + col + 1);
                float4 c = acc[mt][nt];
                *(float2*)(C + (size_t)r0*N + col)     = make_float2(c.x + bx2, c.y + by);
                *(float2*)(C + (size_t)(r0+8)*N + col) = make_float2(c.z + bx2, c.w + by);
            }
        }
    } else {
        int hsel = (bn + warp_n) >> 6;
        #pragma unroll
        for (int mt = 0; mt < 4; mt++) {
            int r0 = bm + warp_m + mt*16 + g;
            int r1 = r0 + 8;
            int p0 = g_inv[(size_t)r0*HH + hsel];
            int p1 = g_inv[(size_t)r1*HH + hsel];
            size_t o0 = ((size_t)(r0 & ~(SS-1)) + p0) * (size_t)N;
            size_t o1 = ((size_t)(r1 & ~(SS-1)) + p1) * (size_t)N;
            #pragma unroll
            for (int nt = 0; nt < 4; nt++) {
                int col = bn + warp_n + nt*8 + 2*tg;
                float bx2 = __ldg(bias + col), by = __ldg(bias + col + 1);
                float4 c = acc[mt][nt];
                *(float2*)(C + o0 + col) = make_float2(c.x + bx2, c.y + by);
                *(float2*)(C + o1 + col) = make_float2(c.z + bx2, c.w + by);
            }
        }
    }
}

// ---------------- 4) attention: register softmax, Q doubles as K-half0 ----------------
#define SST 260
#define QST 68
#define VST 72

__global__ void __launch_bounds__(512) attn_kernel() {
    extern __shared__ float smem[];
    float* sS = smem;                            // 128 x SST (P)
    float* sQ = smem + 128*SST;                  // 128 x QST (Q == K half0)
    float* sK = sQ + 128*QST;                    // 128 x QST (K half1)
    float* sV = sQ;                              // 256 x VST overlay
    float* red = smem + 128*SST + 2*128*QST + 1024;  // 512 floats

    int tid = threadIdx.x;
    int lane = tid & 31, wid = tid >> 5;
    int g = lane >> 2, tg = lane & 3;
    int mt = wid & 7;
    int ng = wid >> 3;                // 0/1 (col group)
    int warp_m = mt * 16;
    int warp_n = ng * 64;             // 64-col slice within each 128-col half
    int warp_nV = ng * 32;

    int n = blockIdx.x, h = blockIdx.y, b = blockIdx.z;
    int base = n * BSZ;
    const float* qkp = g_qk + (size_t)b*SS*DD + h*DH;
    const float* vp  = g_v  + (size_t)b*SS*DD + h*DH;
    const float scale = 0.03125f;

    uint32_t sqb = (uint32_t)__cvta_generic_to_shared(sQ);
    uint32_t skb = (uint32_t)__cvta_generic_to_shared(sK);
    uint32_t svb = (uint32_t)__cvta_generic_to_shared(sV);

    // Q (== K half0; rows never wrap for n<=31) + K half1
    for (int p = tid; p < 128*16; p += 512) {
        int r = p >> 4, seg = p & 15;
        cpa16(sqb + (r*QST + seg*4)*4, qkp + (size_t)(base + r)*DD + seg*4);
    }
    for (int p = tid; p < 128*16; p += 512) {
        int r = p >> 4, seg = p & 15;
        cpa16(skb + (r*QST + seg*4)*4,
              qkp + (size_t)((base + 128 + r) & (SS-1))*DD + seg*4);
    }
    asm volatile("cp.async.commit_group;\n");
    asm volatile("cp.async.wait_group 0;\n");
    __syncthreads();

    // ---- scores: both halves, 8 n-tiles each (FULL 64-col coverage per warp) ----
    float4 acc[2][8];
    #pragma unroll
    for (int i = 0; i < 2; i++)
        #pragma unroll
        for (int j = 0; j < 8; j++) acc[i][j] = make_float4(0.f,0.f,0.f,0.f);

    #pragma unroll 1
    for (int hf = 0; hf < 2; hf++) {
        const float* Bsrc = hf ? sK : sQ;
        #pragma unroll
        for (int ks = 0; ks < 8; ks++) {
            int kc = ks * 8;
            uint32_t a[4], bfr[8][2];
            a[0] = tf32u(sQ[(warp_m+g  )*QST + kc+tg  ]);
            a[1] = tf32u(sQ[(warp_m+g+8)*QST + kc+tg  ]);
            a[2] = tf32u(sQ[(warp_m+g  )*QST + kc+tg+4]);
            a[3] = tf32u(sQ[(warp_m+g+8)*QST + kc+tg+4]);
            #pragma unroll
            for (int nt = 0; nt < 8; nt++) {
                int n0 = warp_n + nt*8;
                bfr[nt][0] = tf32u(Bsrc[(n0+g)*QST + kc+tg  ]);
                bfr[nt][1] = tf32u(Bsrc[(n0+g)*QST + kc+tg+4]);
            }
            #pragma unroll
            for (int nt = 0; nt < 8; nt++)
                mma_tf32(acc[hf][nt], a[0],a[1],a[2],a[3], bfr[nt][0], bfr[nt][1]);
        }
    }

    // scale + self-mask (half0 only)
    int i0 = warp_m + g;
    #pragma unroll
    for (int hf = 0; hf < 2; hf++) {
        #pragma unroll
        for (int nt = 0; nt < 8; nt++) {
            int j0 = warp_n + nt*8 + 2*tg;
            float4 c = acc[hf][nt];
            c.x *= scale; c.y *= scale; c.z *= scale; c.w *= scale;
            if (hf == 0) {
                if (j0   == i0  ) c.x = -INFINITY;
                if (j0+1 == i0  ) c.y = -INFINITY;
                if (j0   == i0+8) c.z = -INFINITY;
                if (j0+1 == i0+8) c.w = -INFINITY;
            }
            acc[hf][nt] = c;
        }
    }
    __syncthreads();     // all warps done reading sQ/sK

    // V load overlaps softmax (overwrites sQ/sK region)
    for (int p = tid; p < 256*16; p += 512) {
        int j = p >> 4, seg = p & 15;
        cpa16(svb + (j*VST + seg*4)*4, vp + (size_t)((base + j) & (SS-1))*DD + seg*4);
    }
    asm volatile("cp.async.commit_group;\n");

    // ---- register softmax ----
    float* redM = red;          // [2][128]
    float* redS = red + 256;    // [2][128]
    float m0 = -INFINITY, m1 = -INFINITY;
    #pragma unroll
    for (int hf = 0; hf < 2; hf++)
        #pragma unroll
        for (int nt = 0; nt < 8; nt++) {
            float4 c = acc[hf][nt];
            m0 = fmaxf(m0, fmaxf(c.x, c.y));
            m1 = fmaxf(m1, fmaxf(c.z, c.w));
        }
    m0 = fmaxf(m0, __shfl_xor_sync(0xffffffffu, m0, 1));
    m0 = fmaxf(m0, __shfl_xor_sync(0xffffffffu, m0, 2));
    m1 = fmaxf(m1, __shfl_xor_sync(0xffffffffu, m1, 1));
    m1 = fmaxf(m1, __shfl_xor_sync(0xffffffffu, m1, 2));
    if (tg == 0) {
        redM[ng*128 + warp_m + g]     = m0;
        redM[ng*128 + warp_m + g + 8] = m1;
    }
    __syncthreads();
    float mg0 = fmaxf(redM[warp_m + g],     redM[128 + warp_m + g]);
    float mg1 = fmaxf(redM[warp_m + g + 8], redM[128 + warp_m + g + 8]);

    float s0 = 0.f, s1 = 0.f;
    #pragma unroll
    for (int hf = 0; hf < 2; hf++)
        #pragma unroll
        for (int nt = 0; nt < 8; nt++) {
            float4 c = acc[hf][nt];
            c.x = __expf(c.x - mg0); c.y = __expf(c.y - mg0);
            c.z = __expf(c.z - mg1); c.w = __expf(c.w - mg1);
            s0 += c.x + c.y; s1 += c.z + c.w;
            acc[hf][nt] = c;
        }
    s0 += __shfl_xor_sync(0xffffffffu, s0, 1);
    s0 += __shfl_xor_sync(0xffffffffu, s0, 2);
    s1 += __shfl_xor_sync(0xffffffffu, s1, 1);
    s1 += __shfl_xor_sync(0xffffffffu, s1, 2);
    if (tg == 0) {
        redS[ng*128 + warp_m + g]     = s0;
        redS[ng*128 + warp_m + g + 8] = s1;
    }
    __syncthreads();
    float inv0 = 1.f / (redS[warp_m + g]     + redS[128 + warp_m + g]);
    float inv1 = 1.f / (redS[warp_m + g + 8] + redS[128 + warp_m + g + 8]);

    // P = tf32r(p/sum) -> single smem write
    #pragma unroll
    for (int hf = 0; hf < 2; hf++)
        #pragma unroll
        for (int nt = 0; nt < 8; nt++) {
            int col = hf*128 + warp_n + nt*8 + 2*tg;
            float4 c = acc[hf][nt];
            *(float2*)&sS[(i0  )*SST + col] = make_float2(tf32r(c.x*inv0), tf32r(c.y*inv0));
            *(float2*)&sS[(i0+8)*SST + col] = make_float2(tf32r(c.z*inv1), tf32r(c.w*inv1));
        }

    asm volatile("cp.async.wait_group 0;\n");
    __syncthreads();

    // ---- PV: out[128x64] = P[128x256] @ V[256x64] ----
    float4 o[4];
    #pragma unroll
    for (int j = 0; j < 4; j++) o[j] = make_float4(0.f,0.f,0.f,0.f);

    #pragma unroll 4
    for (int ks = 0; ks < 32; ks++) {
        int kc = ks * 8;
        uint32_t a[4], bfr[4][2];
        a[0] = __float_as_uint(sS[(warp_m+g  )*SST + kc+tg  ]);
        a[1] = __float_as_uint(sS[(warp_m+g+8)*SST + kc+tg  ]);
        a[2] = __float_as_uint(sS[(warp_m+g  )*SST + kc+tg+4]);
        a[3] = __float_as_uint(sS[(warp_m+g+8)*SST + kc+tg+4]);
        #pragma unroll
        for (int nt = 0; nt < 4; nt++) {
            int n0 = warp_nV + nt*8;
            bfr[nt][0] = tf32u(sV[(kc+tg  )*VST + n0+g]);
            bfr[nt][1] = tf32u(sV[(kc+tg+4)*VST + n0+g]);
        }
        #pragma unroll
        for (int nt = 0; nt < 4; nt++)
            mma_tf32(o[nt], a[0],a[1],a[2],a[3], bfr[nt][0], bfr[nt][1]);
    }

    float* outp = g_outs + (size_t)b*SS*DD + h*DH;
    {
        int t0 = base + i0;
        #pragma unroll
        for (int nt = 0; nt < 4; nt++) {
            int d0 = warp_nV + nt*8 + 2*tg;
            float4 c = o[nt];
            *(float2*)(outp + (size_t)t0*DD + d0)     = make_float2(c.x, c.y);
            *(float2*)(outp + (size_t)(t0+8)*DD + d0) = make_float2(c.z, c.w);
            if (d0 == 0) {
                g_ch0[((size_t)b*SS + t0  )*HH + h] = c.x;
                g_ch0[((size_t)b*SS + t0+8)*HH + h] = c.z;
            }
        }
    }
}

// ---------------- 5) feature-0-only inverse scatter ----------------
__global__ void __launch_bounds__(256) scatter_kernel() {
    int i = blockIdx.x*256 + threadIdx.x;
    if (i >= BB*SS*HH) return;
    int h = i % HH;
    int b = i / (SS*HH);
    int p = g_idx[i];
    g_outs[((size_t)b*SS + p)*DD + h*DH] = g_ch0[i];
}

// ---------------- launch ----------------
extern "C" void kernel_launch(void* const* d_in, const int* in_sizes, int n_in,
                              void* d_out, int out_size) {
    const float* x  = (const float*)d_in[0];
    const float* Wh = (const float*)d_in[1];
    const float* Wq = (const float*)d_in[2];
    const float* bq = (const float*)d_in[3];
    const float* Wv = (const float*)d_in[4];
    const float* bv = (const float*)d_in[5];
    const float* Wo = (const float*)d_in[6];
    const float* bo = (const float*)d_in[7];
    float* out = (float*)d_out;

    float* qkp; cudaGetSymbolAddress((void**)&qkp, g_qk);
    float* vp;  cudaGetSymbolAddress((void**)&vp,  g_v);
    float* osp; cudaGetSymbolAddress((void**)&osp, g_outs);

    const int M = BB*SS;

    hash_kernel<<<M/32, 256>>>(x, Wh);
    sort_kernel<<<BB*HH, 1024>>>();

    size_t gsmem = (size_t)(4*128*AST) * sizeof(float);
    cudaFuncSetAttribute(gemm3, cudaFuncAttributeMaxDynamicSharedMemorySize, (int)gsmem);
    gemm3<<<dim3(16, M/128), 256, gsmem>>>(x, Wq, bq, qkp, Wv, bv, vp, 8, DD, DD, 1);

    size_t asmem = (size_t)(128*SST + 2*128*QST + 1024 + 512) * sizeof(float);  // 208,896 B
    cudaFuncSetAttribute(attn_kernel, cudaFuncAttributeMaxDynamicSharedMemorySize, (int)asmem);
    dim3 ag(NB, HH, BB);
    attn_kernel<<<ag, 512, asmem>>>();

    scatter_kernel<<<(BB*SS*HH + 255)/256, 256>>>();
    gemm3<<<dim3(8, M/128), 256, gsmem>>>(osp, Wo, bo, out, Wo, bo, out, 8, DD, DD, 0);
}

// round 15
// speedup vs baseline: 1.1519x; 1.0202x over previous
#include <cuda_runtime.h>
#include <math.h>
#include <stdint.h>

#define BB 4
#define SS 4096
#define DD 1024
#define HH 16
#define DH 64
#define BSZ 128
#define NB 32
#define EPSF 1e-4f

// ---------------- scratch ----------------
__device__ float g_angles[BB*SS*HH];
__device__ int   g_idx[BB*SS*HH];
__device__ int   g_inv[BB*SS*HH];
__device__ float g_qk[(size_t)BB*SS*DD];    // SORTED per head
__device__ float g_v [(size_t)BB*SS*DD];    // SORTED per head
__device__ float g_outs[(size_t)BB*SS*DD];
__device__ float g_ch0[BB*SS*HH];

__device__ __forceinline__ float tf32r(float x) {
    uint32_t u;
    asm("cvt.rna.tf32.f32 %0, %1;" : "=r"(u) : "f"(x));
    return __uint_as_float(u);
}
__device__ __forceinline__ uint32_t tf32u(float x) {
    uint32_t u;
    asm("cvt.rna.tf32.f32 %0, %1;" : "=r"(u) : "f"(x));
    return u;
}

__device__ __forceinline__ void mma_tf32(float4& d,
                                         uint32_t a0, uint32_t a1, uint32_t a2, uint32_t a3,
                                         uint32_t b0, uint32_t b1) {
    asm volatile(
        "mma.sync.aligned.m16n8k8.row.col.f32.tf32.tf32.f32 "
        "{%0,%1,%2,%3},{%4,%5,%6,%7},{%8,%9},{%0,%1,%2,%3};"
        : "+f"(d.x), "+f"(d.y), "+f"(d.z), "+f"(d.w)
        : "r"(a0), "r"(a1), "r"(a2), "r"(a3), "r"(b0), "r"(b1));
}

__device__ __forceinline__ void cpa16(uint32_t saddr, const float* g) {
    asm volatile("cp.async.cg.shared.global [%0], [%1], 16;\n" :: "r"(saddr), "l"(g));
}

__device__ __forceinline__ unsigned long long shfl64(unsigned long long v, int lanemask) {
    uint32_t lo = (uint32_t)v, hi = (uint32_t)(v >> 32);
    lo = __shfl_xor_sync(0xffffffffu, lo, lanemask);
    hi = __shfl_xor_sync(0xffffffffu, hi, lanemask);
    return ((unsigned long long)hi << 32) | lo;
}
__device__ __forceinline__ void cswap(unsigned long long& a, unsigned long long& b, bool up) {
    if ((a > b) == up) { unsigned long long t = a; a = b; b = t; }
}

// ---------------- 1) hash v2 (bit-identical chains) ----------------
__global__ void __launch_bounds__(256) hash_kernel(const float* __restrict__ x,
                                                   const float* __restrict__ Wh) {
    __shared__ float4 xs4[32][64];
    __shared__ float  hs[32][33];
    int tid = threadIdx.x;
    int g  = tid & 31;
    int o0 = (tid >> 5) * 4;
    int tok0 = blockIdx.x * 32;
    const float4* xbase = (const float4*)(x + (size_t)tok0 * DD);
    const float4* w4 = (const float4*)Wh;

    float acc0 = 0.f, acc1 = 0.f, acc2 = 0.f, acc3 = 0.f;
    for (int c = 0; c < 4; c++) {
        __syncthreads();
        #pragma unroll
        for (int i = 0; i < 8; i++) {
            int idx = tid + i*256;
            int r = idx >> 6, k4 = idx & 63;
            xs4[r][k4 ^ (r & 7)] = xbase[(size_t)r*(DD/4) + c*64 + k4];
        }
        __syncthreads();
        const float4* wr0 = w4 + (size_t)(o0+0)*(DD/4) + c*64;
        const float4* wr1 = w4 + (size_t)(o0+1)*(DD/4) + c*64;
        const float4* wr2 = w4 + (size_t)(o0+2)*(DD/4) + c*64;
        const float4* wr3 = w4 + (size_t)(o0+3)*(DD/4) + c*64;
        #pragma unroll 8
        for (int k4 = 0; k4 < 64; k4++) {
            float4 xv = xs4[g][k4 ^ (g & 7)];
            float4 w0 = __ldg(wr0 + k4);
            float4 w1 = __ldg(wr1 + k4);
            float4 w2 = __ldg(wr2 + k4);
            float4 w3 = __ldg(wr3 + k4);
            acc0 = fmaf(xv.x, w0.x, acc0); acc0 = fmaf(xv.y, w0.y, acc0);
            acc0 = fmaf(xv.z, w0.z, acc0); acc0 = fmaf(xv.w, w0.w, acc0);
            acc1 = fmaf(xv.x, w1.x, acc1); acc1 = fmaf(xv.y, w1.y, acc1);
            acc1 = fmaf(xv.z, w1.z, acc1); acc1 = fmaf(xv.w, w1.w, acc1);
            acc2 = fmaf(xv.x, w2.x, acc2); acc2 = fmaf(xv.y, w2.y, acc2);
            acc2 = fmaf(xv.z, w2.z, acc2); acc2 = fmaf(xv.w, w2.w, acc2);
            acc3 = fmaf(xv.x, w3.x, acc3); acc3 = fmaf(xv.y, w3.y, acc3);
            acc3 = fmaf(xv.z, w3.z, acc3); acc3 = fmaf(xv.w, w3.w, acc3);
        }
    }
    hs[g][o0]   = acc0;
    hs[g][o0+1] = acc1;
    hs[g][o0+2] = acc2;
    hs[g][o0+3] = acc3;
    __syncthreads();
    for (int i = tid; i < 32*HH; i += 256) {
        int gg = i >> 4, hh = i & 15;
        float h0 = hs[gg][2*hh], h1 = hs[gg][2*hh+1];
        g_angles[(size_t)(tok0 + gg)*HH + hh] = __fdiv_rn(h0, h1 + EPSF);
    }
}

// ---------------- 2) bitonic argsort v2: u64 packed keys, register/shuffle resident ----
// Produces the SAME permutation as stable argsort on (angle, index).
__global__ void __launch_bounds__(1024) sort_kernel() {
    int b = blockIdx.x / HH, h = blockIdx.x % HH;
    __shared__ unsigned long long sk[SS];
    int tid = threadIdx.x;
    int e0 = 4 * tid;

    unsigned long long v[4];
    #pragma unroll
    for (int q = 0; q < 4; q++) {
        int e = e0 + q;
        uint32_t u = __float_as_uint(g_angles[((size_t)b*SS + e)*HH + h]);
        u ^= (u & 0x80000000u) ? 0xFFFFFFFFu : 0x80000000u;   // monotone float->uint
        v[q] = ((unsigned long long)u << 32) | (uint32_t)e;
    }

    for (int k = 2; k <= SS; k <<= 1) {
        int j = k >> 1;
        if (j >= 128) {
            // cross-warp strides in smem
            #pragma unroll
            for (int q = 0; q < 4; q++) sk[e0 + q] = v[q];
            __syncthreads();
            for (; j >= 128; j >>= 1) {
                #pragma unroll
                for (int t2 = 0; t2 < 2; t2++) {
                    int i2 = tid + t2*1024;
                    int i = ((i2 & ~(j-1)) << 1) | (i2 & (j-1));
                    int ixj = i + j;
                    bool up = ((i & k) == 0);
                    unsigned long long a = sk[i], c = sk[ixj];
                    if ((a > c) == up) { sk[i] = c; sk[ixj] = a; }
                }
                __syncthreads();
            }
            #pragma unroll
            for (int q = 0; q < 4; q++) v[q] = sk[e0 + q];
        }
        // warp-shuffle strides j = 64..4 (partner thread = tid ^ (j/4), same warp)
        for (; j >= 4; j >>= 1) {
            int pl = j >> 2;
            bool keepmin = (((tid & pl) == 0) == ((e0 & k) == 0));
            #pragma unroll
            for (int q = 0; q < 4; q++) {
                unsigned long long o = shfl64(v[q], pl);
                unsigned long long mn = v[q] < o ? v[q] : o;
                unsigned long long mx = v[q] < o ? o : v[q];
                v[q] = keepmin ? mn : mx;
            }
        }
        // intra-thread strides j=2 (only when k>=4) and j=1
        if (k >= 4) {
            bool up = ((e0 & k) == 0);
            cswap(v[0], v[2], up);
            cswap(v[1], v[3], up);
        }
        {
            bool up0 = (((e0    ) & k) == 0);
            bool up1 = (((e0 + 2) & k) == 0);
            cswap(v[0], v[1], up0);
            cswap(v[2], v[3], up1);
        }
    }

    #pragma unroll
    for (int q = 0; q < 4; q++) {
        int e = e0 + q;
        int orig = (int)(v[q] & 0xFFFFFFFFu);
        g_idx[((size_t)b*SS + e)*HH + h]    = orig;
        g_inv[((size_t)b*SS + orig)*HH + h] = e;
    }
}

// ---------------- 3) TF32 GEMM: 128x128x32, 2-stage cp.async, 2 blocks/SM ----
#define AST 36

__global__ void __launch_bounds__(256, 2) gemm3(const float* __restrict__ A,
                                                const float* __restrict__ W0,
                                                const float* __restrict__ b0,
                                                float* __restrict__ C0,
                                                const float* __restrict__ W1,
                                                const float* __restrict__ b1,
                                                float* __restrict__ C1,
                                                int split, int N, int K, int mode) {
    extern __shared__ float smem[];
    float* As = smem;
    float* Bs = smem + 2*128*AST;

    const float* W; const float* bias; float* C;
    int bx = blockIdx.x;
    if (bx < split) { W = W0; bias = b0; C = C0; }
    else            { W = W1; bias = b1; C = C1; bx -= split; }
    int bm = blockIdx.y * 128, bn = bx * 128;

    int tid  = threadIdx.x;
    int lane = tid & 31, wid = tid >> 5;
    int g = lane >> 2, tg = lane & 3;
    int warp_m = (wid & 1) * 64;
    int warp_n = (wid >> 1) * 32;

    float4 acc[4][4];
    #pragma unroll
    for (int i = 0; i < 4; i++)
        #pragma unroll
        for (int j = 0; j < 4; j++) acc[i][j] = make_float4(0.f,0.f,0.f,0.f);

    auto load_tile = [&](int k0, int buf) {
        uint32_t abase = (uint32_t)__cvta_generic_to_shared(As + buf*128*AST);
        uint32_t bbase = (uint32_t)__cvta_generic_to_shared(Bs + buf*128*AST);
        #pragma unroll
        for (int i = 0; i < 4; i++) {
            int idx = tid + i*256;
            int r = idx >> 3, c4 = (idx & 7) * 4;
            cpa16(abase + (r*AST + c4)*4, A + (size_t)(bm + r)*K + k0 + c4);
            cpa16(bbase + (r*AST + c4)*4, W + (size_t)(bn + r)*K + k0 + c4);
        }
        asm volatile("cp.async.commit_group;\n");
    };

    load_tile(0, 0);

    int nkt = K / 32;
    for (int kt = 0; kt < nkt; kt++) {
        int cur = kt & 1;
        if (kt + 1 < nkt) {
            load_tile((kt + 1) * 32, (kt + 1) & 1);
            asm volatile("cp.async.wait_group 1;\n");
        } else {
            asm volatile("cp.async.wait_group 0;\n");
        }
        __syncthreads();

        const float* Ab = As + cur*128*AST;
        const float* Bb = Bs + cur*128*AST;
        #pragma unroll
        for (int ks = 0; ks < 4; ks++) {
            int kc = ks * 8;
            uint32_t a[4][4], b[4][2];
            #pragma unroll
            for (int mt = 0; mt < 4; mt++) {
                int r0 = warp_m + mt*16;
                a[mt][0] = tf32u(Ab[(r0+g  )*AST + kc+tg  ]);
                a[mt][1] = tf32u(Ab[(r0+g+8)*AST + kc+tg  ]);
                a[mt][2] = tf32u(Ab[(r0+g  )*AST + kc+tg+4]);
                a[mt][3] = tf32u(Ab[(r0+g+8)*AST + kc+tg+4]);
            }
            #pragma unroll
            for (int nt = 0; nt < 4; nt++) {
                int n0 = warp_n + nt*8;
                b[nt][0] = tf32u(Bb[(n0+g)*AST + kc+tg  ]);
                b[nt][1] = tf32u(Bb[(n0+g)*AST + kc+tg+4]);
            }
            #pragma unroll
            for (int mt = 0; mt < 4; mt++)
                #pragma unroll
                for (int nt = 0; nt < 4; nt++)
                    mma_tf32(acc[mt][nt], a[mt][0],a[mt][1],a[mt][2],a[mt][3],
                             b[nt][0], b[nt][1]);
        }
        __syncthreads();
    }

    if (mode == 0) {
        #pragma unroll
        for (int mt = 0; mt < 4; mt++) {
            int r0 = bm + warp_m + mt*16 + g;
            #pragma unroll
            for (int nt = 0; nt < 4; nt++) {
                int col = bn + warp_n + nt*8 + 2*tg;
                float bx2 = __ldg(bias + col), by = __ldg(bias + col + 1);
                float4 c = acc[mt][nt];
                *(float2*)(C + (size_t)r0*N + col)     = make_float2(c.x + bx2, c.y + by);
                *(float2*)(C + (size_t)(r0+8)*N + col) = make_float2(c.z + bx2, c.w + by);
            }
        }
    } else {
        int hsel = (bn + warp_n) >> 6;
        #pragma unroll
        for (int mt = 0; mt < 4; mt++) {
            int r0 = bm + warp_m + mt*16 + g;
            int r1 = r0 + 8;
            int p0 = g_inv[(size_t)r0*HH + hsel];
            int p1 = g_inv[(size_t)r1*HH + hsel];
            size_t o0 = ((size_t)(r0 & ~(SS-1)) + p0) * (size_t)N;
            size_t o1 = ((size_t)(r1 & ~(SS-1)) + p1) * (size_t)N;
            #pragma unroll
            for (int nt = 0; nt < 4; nt++) {
                int col = bn + warp_n + nt*8 + 2*tg;
                float bx2 = __ldg(bias + col), by = __ldg(bias + col + 1);
                float4 c = acc[mt][nt];
                *(float2*)(C + o0 + col) = make_float2(c.x + bx2, c.y + by);
                *(float2*)(C + o1 + col) = make_float2(c.z + bx2, c.w + by);
            }
        }
    }
}

// ---------------- 4) attention: register softmax, Q doubles as K-half0 ----------------
#define SST 260
#define QST 68
#define VST 72

__global__ void __launch_bounds__(512) attn_kernel() {
    extern __shared__ float smem[];
    float* sS = smem;                            // 128 x SST (P)
    float* sQ = smem + 128*SST;                  // 128 x QST (Q == K half0)
    float* sK = sQ + 128*QST;                    // 128 x QST (K half1)
    float* sV = sQ;                              // 256 x VST overlay
    float* red = smem + 128*SST + 2*128*QST + 1024;  // 512 floats

    int tid = threadIdx.x;
    int lane = tid & 31, wid = tid >> 5;
    int g = lane >> 2, tg = lane & 3;
    int mt = wid & 7;
    int ng = wid >> 3;
    int warp_m = mt * 16;
    int warp_n = ng * 64;
    int warp_nV = ng * 32;

    int n = blockIdx.x, h = blockIdx.y, b = blockIdx.z;
    int base = n * BSZ;
    const float* qkp = g_qk + (size_t)b*SS*DD + h*DH;
    const float* vp  = g_v  + (size_t)b*SS*DD + h*DH;
    const float scale = 0.03125f;

    uint32_t sqb = (uint32_t)__cvta_generic_to_shared(sQ);
    uint32_t skb = (uint32_t)__cvta_generic_to_shared(sK);
    uint32_t svb = (uint32_t)__cvta_generic_to_shared(sV);

    for (int p = tid; p < 128*16; p += 512) {
        int r = p >> 4, seg = p & 15;
        cpa16(sqb + (r*QST + seg*4)*4, qkp + (size_t)(base + r)*DD + seg*4);
    }
    for (int p = tid; p < 128*16; p += 512) {
        int r = p >> 4, seg = p & 15;
        cpa16(skb + (r*QST + seg*4)*4,
              qkp + (size_t)((base + 128 + r) & (SS-1))*DD + seg*4);
    }
    asm volatile("cp.async.commit_group;\n");
    asm volatile("cp.async.wait_group 0;\n");
    __syncthreads();

    float4 acc[2][8];
    #pragma unroll
    for (int i = 0; i < 2; i++)
        #pragma unroll
        for (int j = 0; j < 8; j++) acc[i][j] = make_float4(0.f,0.f,0.f,0.f);

    #pragma unroll 1
    for (int hf = 0; hf < 2; hf++) {
        const float* Bsrc = hf ? sK : sQ;
        #pragma unroll
        for (int ks = 0; ks < 8; ks++) {
            int kc = ks * 8;
            uint32_t a[4], bfr[8][2];
            a[0] = tf32u(sQ[(warp_m+g  )*QST + kc+tg  ]);
            a[1] = tf32u(sQ[(warp_m+g+8)*QST + kc+tg  ]);
            a[2] = tf32u(sQ[(warp_m+g  )*QST + kc+tg+4]);
            a[3] = tf32u(sQ[(warp_m+g+8)*QST + kc+tg+4]);
            #pragma unroll
            for (int nt = 0; nt < 8; nt++) {
                int n0 = warp_n + nt*8;
                bfr[nt][0] = tf32u(Bsrc[(n0+g)*QST + kc+tg  ]);
                bfr[nt][1] = tf32u(Bsrc[(n0+g)*QST + kc+tg+4]);
            }
            #pragma unroll
            for (int nt = 0; nt < 8; nt++)
                mma_tf32(acc[hf][nt], a[0],a[1],a[2],a[3], bfr[nt][0], bfr[nt][1]);
        }
    }

    int i0 = warp_m + g;
    #pragma unroll
    for (int hf = 0; hf < 2; hf++) {
        #pragma unroll
        for (int nt = 0; nt < 8; nt++) {
            int j0 = warp_n + nt*8 + 2*tg;
            float4 c = acc[hf][nt];
            c.x *= scale; c.y *= scale; c.z *= scale; c.w *= scale;
            if (hf == 0) {
                if (j0   == i0  ) c.x = -INFINITY;
                if (j0+1 == i0  ) c.y = -INFINITY;
                if (j0   == i0+8) c.z = -INFINITY;
                if (j0+1 == i0+8) c.w = -INFINITY;
            }
            acc[hf][nt] = c;
        }
    }
    __syncthreads();

    for (int p = tid; p < 256*16; p += 512) {
        int j = p >> 4, seg = p & 15;
        cpa16(svb + (j*VST + seg*4)*4, vp + (size_t)((base + j) & (SS-1))*DD + seg*4);
    }
    asm volatile("cp.async.commit_group;\n");

    float* redM = red;
    float* redS = red + 256;
    float m0 = -INFINITY, m1 = -INFINITY;
    #pragma unroll
    for (int hf = 0; hf < 2; hf++)
        #pragma unroll
        for (int nt = 0; nt < 8; nt++) {
            float4 c = acc[hf][nt];
            m0 = fmaxf(m0, fmaxf(c.x, c.y));
            m1 = fmaxf(m1, fmaxf(c.z, c.w));
        }
    m0 = fmaxf(m0, __shfl_xor_sync(0xffffffffu, m0, 1));
    m0 = fmaxf(m0, __shfl_xor_sync(0xffffffffu, m0, 2));
    m1 = fmaxf(m1, __shfl_xor_sync(0xffffffffu, m1, 1));
    m1 = fmaxf(m1, __shfl_xor_sync(0xffffffffu, m1, 2));
    if (tg == 0) {
        redM[ng*128 + warp_m + g]     = m0;
        redM[ng*128 + warp_m + g + 8] = m1;
    }
    __syncthreads();
    float mg0 = fmaxf(redM[warp_m + g],     redM[128 + warp_m + g]);
    float mg1 = fmaxf(redM[warp_m + g + 8], redM[128 + warp_m + g + 8]);

    float s0 = 0.f, s1 = 0.f;
    #pragma unroll
    for (int hf = 0; hf < 2; hf++)
        #pragma unroll
        for (int nt = 0; nt < 8; nt++) {
            float4 c = acc[hf][nt];
            c.x = __expf(c.x - mg0); c.y = __expf(c.y - mg0);
            c.z = __expf(c.z - mg1); c.w = __expf(c.w - mg1);
            s0 += c.x + c.y; s1 += c.z + c.w;
            acc[hf][nt] = c;
        }
    s0 += __shfl_xor_sync(0xffffffffu, s0, 1);
    s0 += __shfl_xor_sync(0xffffffffu, s0, 2);
    s1 += __shfl_xor_sync(0xffffffffu, s1, 1);
    s1 += __shfl_xor_sync(0xffffffffu, s1, 2);
    if (tg == 0) {
        redS[ng*128 + warp_m + g]     = s0;
        redS[ng*128 + warp_m + g + 8] = s1;
    }
    __syncthreads();
    float inv0 = 1.f / (redS[warp_m + g]     + redS[128 + warp_m + g]);
    float inv1 = 1.f / (redS[warp_m + g + 8] + redS[128 + warp_m + g + 8]);

    #pragma unroll
    for (int hf = 0; hf < 2; hf++)
        #pragma unroll
        for (int nt = 0; nt < 8; nt++) {
            int col = hf*128 + warp_n + nt*8 + 2*tg;
            float4 c = acc[hf][nt];
            *(float2*)&sS[(i0  )*SST + col] = make_float2(tf32r(c.x*inv0), tf32r(c.y*inv0));
            *(float2*)&sS[(i0+8)*SST + col] = make_float2(tf32r(c.z*inv1), tf32r(c.w*inv1));
        }

    asm volatile("cp.async.wait_group 0;\n");
    __syncthreads();

    float4 o[4];
    #pragma unroll
    for (int j = 0; j < 4; j++) o[j] = make_float4(0.f,0.f,0.f,0.f);

    #pragma unroll 4
    for (int ks = 0; ks < 32; ks++) {
        int kc = ks * 8;
        uint32_t a[4], bfr[4][2];
        a[0] = __float_as_uint(sS[(warp_m+g  )*SST + kc+tg  ]);
        a[1] = __float_as_uint(sS[(warp_m+g+8)*SST + kc+tg  ]);
        a[2] = __float_as_uint(sS[(warp_m+g  )*SST + kc+tg+4]);
        a[3] = __float_as_uint(sS[(warp_m+g+8)*SST + kc+tg+4]);
        #pragma unroll
        for (int nt = 0; nt < 4; nt++) {
            int n0 = warp_nV + nt*8;
            bfr[nt][0] = tf32u(sV[(kc+tg  )*VST + n0+g]);
            bfr[nt][1] = tf32u(sV[(kc+tg+4)*VST + n0+g]);
        }
        #pragma unroll
        for (int nt = 0; nt < 4; nt++)
            mma_tf32(o[nt], a[0],a[1],a[2],a[3], bfr[nt][0], bfr[nt][1]);
    }

    float* outp = g_outs + (size_t)b*SS*DD + h*DH;
    {
        int t0 = base + i0;
        #pragma unroll
        for (int nt = 0; nt < 4; nt++) {
            int d0 = warp_nV + nt*8 + 2*tg;
            float4 c = o[nt];
            *(float2*)(outp + (size_t)t0*DD + d0)     = make_float2(c.x, c.y);
            *(float2*)(outp + (size_t)(t0+8)*DD + d0) = make_float2(c.z, c.w);
            if (d0 == 0) {
                g_ch0[((size_t)b*SS + t0  )*HH + h] = c.x;
                g_ch0[((size_t)b*SS + t0+8)*HH + h] = c.z;
            }
        }
    }
}

// ---------------- 5) feature-0-only inverse scatter ----------------
__global__ void __launch_bounds__(256) scatter_kernel() {
    int i = blockIdx.x*256 + threadIdx.x;
    if (i >= BB*SS*HH) return;
    int h = i % HH;
    int b = i / (SS*HH);
    int p = g_idx[i];
    g_outs[((size_t)b*SS + p)*DD + h*DH] = g_ch0[i];
}

// ---------------- launch ----------------
extern "C" void kernel_launch(void* const* d_in, const int* in_sizes, int n_in,
                              void* d_out, int out_size) {
    const float* x  = (const float*)d_in[0];
    const float* Wh = (const float*)d_in[1];
    const float* Wq = (const float*)d_in[2];
    const float* bq = (const float*)d_in[3];
    const float* Wv = (const float*)d_in[4];
    const float* bv = (const float*)d_in[5];
    const float* Wo = (const float*)d_in[6];
    const float* bo = (const float*)d_in[7];
    float* out = (float*)d_out;

    float* qkp; cudaGetSymbolAddress((void**)&qkp, g_qk);
    float* vp;  cudaGetSymbolAddress((void**)&vp,  g_v);
    float* osp; cudaGetSymbolAddress((void**)&osp, g_outs);

    const int M = BB*SS;

    hash_kernel<<<M/32, 256>>>(x, Wh);
    sort_kernel<<<BB*HH, 1024>>>();

    size_t gsmem = (size_t)(4*128*AST) * sizeof(float);
    cudaFuncSetAttribute(gemm3, cudaFuncAttributeMaxDynamicSharedMemorySize, (int)gsmem);
    gemm3<<<dim3(16, M/128), 256, gsmem>>>(x, Wq, bq, qkp, Wv, bv, vp, 8, DD, DD, 1);

    size_t asmem = (size_t)(128*SST + 2*128*QST + 1024 + 512) * sizeof(float);
    cudaFuncSetAttribute(attn_kernel, cudaFuncAttributeMaxDynamicSharedMemorySize, (int)asmem);
    dim3 ag(NB, HH, BB);
    attn_kernel<<<ag, 512, asmem>>>();

    scatter_kernel<<<(BB*SS*HH + 255)/256, 256>>>();
    gemm3<<<dim3(8, M/128), 256, gsmem>>>(osp, Wo, bo, out, Wo, bo, out, 8, DD, DD, 0);
}